// round 7
// baseline (speedup 1.0000x reference)
#include <cuda_runtime.h>
#include <cuda_fp16.h>
#include <math.h>
#include <stdint.h>

// ---------------- problem constants ----------------
#define BATCH 8
#define SEQ   4096
#define F_IN  586
#define KPAD  640            // F_IN padded to multiple of 64
#define DM    512
#define NH    8
#define HD    64
#define FF    1024
#define NLAY  2
#define BS    (BATCH*SEQ) // 32768
#define BH    (BATCH*NH)  // 64
#define QKVN  (3*DM)      // 1536
#define EPS_ATTN 1e-6f
#define EPS_LN   1e-5f

// ---------------- scratch (device globals) ----------------
__device__ __half g_he[BS*KPAD];     // fp16 padded embeddings
__device__ __half g_hx[BS*DM];       // fp16 copy of x (GEMM A operand)
__device__ __half g_hq[BS*DM];       // fp16 q
__device__ __half g_hk[BS*DM];       // fp16 k
__device__ __half g_hv[BS*DM];       // fp16 v
__device__ __half g_ht[BS*DM];       // fp16 attention output
__device__ __half g_hh[BS*FF];       // fp16 FFN hidden
__device__ float  g_x [BS*DM];       // f32 x (residual / LN)
__device__ float  g_y [BS*DM];       // f32 gemm out (pre-LN)
#define NCHUNK 8
#define KV_CH  (SEQ/NCHUNK)
__device__ float g_kvpart[NCHUNK*BH*HD*HD];
__device__ float g_kspart[NCHUNK*BH*HD];
__device__ float g_kv[BH*HD*HD];
__device__ float g_ks[BH*HD];
// fp16 transposed weights [N,K]
__device__ __half g_w0t [DM*KPAD];
__device__ __half g_wqkvt[NLAY*QKVN*DM];
__device__ __half g_wot [NLAY*DM*DM];
__device__ __half g_w1t [NLAY*FF*DM];
__device__ __half g_w2t [NLAY*DM*FF];
__device__ float  g_bqkv[NLAY*QKVN];

// ---------------- helpers ----------------
__device__ __forceinline__ uint32_t smem_u32(const void* p) {
    uint32_t a;
    asm("{ .reg .u64 t; cvta.to.shared.u64 t, %1; cvt.u32.u64 %0, t; }" : "=r"(a) : "l"(p));
    return a;
}
__device__ __forceinline__ void cp_async16(uint32_t dst, const void* src) {
    asm volatile("cp.async.cg.shared.global [%0], [%1], 16;"
                 :: "r"(dst), "l"(src) : "memory");
}
#define CP_COMMIT() asm volatile("cp.async.commit_group;" ::: "memory")

__device__ __forceinline__ void ldmatrix_x4(uint32_t* r, uint32_t addr) {
    asm volatile("ldmatrix.sync.aligned.m8n8.x4.shared.b16 {%0,%1,%2,%3}, [%4];"
                 : "=r"(r[0]), "=r"(r[1]), "=r"(r[2]), "=r"(r[3]) : "r"(addr));
}
__device__ __forceinline__ void mma_f16(float* c, const uint32_t* a, uint32_t b0, uint32_t b1) {
    asm volatile(
        "mma.sync.aligned.m16n8k16.row.col.f32.f16.f16.f32 "
        "{%0,%1,%2,%3}, {%4,%5,%6,%7}, {%8,%9}, {%0,%1,%2,%3};"
        : "+f"(c[0]), "+f"(c[1]), "+f"(c[2]), "+f"(c[3])
        : "r"(a[0]), "r"(a[1]), "r"(a[2]), "r"(a[3]), "r"(b0), "r"(b1));
}

// ---------------- fp16 tensor-core GEMM, 3-stage pipeline ----------------
// act: 0 none, 1 elu+1, 2 relu, 3 qkv-mode (elu+1 for c<1024; fp16 out split
// across Ch/Ch2/Ch3 each [M,512]).
#define GBM 128
#define GBN 128
#define HBK 64
#define TILE_B 16384
#define NSTAGE 3
#define GEMM_SMEM (2*NSTAGE*TILE_B)   // 96 KB

__global__ __launch_bounds__(256) void gemm_h(
    const __half* __restrict__ A, const __half* __restrict__ BT,
    const float* __restrict__ bias, const float* __restrict__ res,
    float* __restrict__ Cf, __half* __restrict__ Ch,
    __half* __restrict__ Ch2, __half* __restrict__ Ch3,
    int M, int N, int K, int act)
{
    extern __shared__ char smraw[];
    const uint32_t smBase = smem_u32(smraw);
    const int tid  = threadIdx.x;
    const int warp = tid >> 5;
    const int lane = tid & 31;
    const int g = lane >> 2;
    const int t = lane & 3;
    const int warpM = warp & 3;
    const int warpN = warp >> 2;
    const int rowBase = blockIdx.y * GBM;
    const int colBase = blockIdx.x * GBN;
    const int kiters = K / HBK;

    auto loadTile = [&](int it, int buf) {
        const int k0 = it * HBK;
#pragma unroll
        for (int p = 0; p < 4; p++) {
            int idx = tid + p * 256;
            int row = idx >> 3, c = idx & 7;
            uint32_t dst = smBase + buf * TILE_B + row * 128 + ((c ^ (row & 7)) << 4);
            cp_async16(dst, &A[(size_t)(rowBase + row) * K + k0 + c * 8]);
        }
#pragma unroll
        for (int p = 0; p < 4; p++) {
            int idx = tid + p * 256;
            int row = idx >> 3, c = idx & 7;
            uint32_t dst = smBase + NSTAGE * TILE_B + buf * TILE_B + row * 128 + ((c ^ (row & 7)) << 4);
            cp_async16(dst, &BT[(size_t)(colBase + row) * K + k0 + c * 8]);
        }
    };

    float acc[2][8][4];
#pragma unroll
    for (int mt = 0; mt < 2; mt++)
#pragma unroll
        for (int nt = 0; nt < 8; nt++)
#pragma unroll
            for (int i = 0; i < 4; i++) acc[mt][nt][i] = 0.f;

    loadTile(0, 0); CP_COMMIT();
    loadTile(1, 1); CP_COMMIT();

    const int lrow = lane & 15;
    const int khalf = lane >> 4;

    for (int it = 0; it < kiters; ++it) {
        if (it + 1 < kiters) {
            asm volatile("cp.async.wait_group 1;" ::: "memory");
        } else {
            asm volatile("cp.async.wait_group 0;" ::: "memory");
        }
        __syncthreads();
        if (it + 2 < kiters) {
            loadTile(it + 2, (it + 2) % NSTAGE);
            CP_COMMIT();
        }
        const int buf = it % NSTAGE;
        const uint32_t Abase = smBase + buf * TILE_B;
        const uint32_t Bbase = smBase + NSTAGE * TILE_B + buf * TILE_B;
#pragma unroll
        for (int ks = 0; ks < 4; ks++) {
            const int cIdx = 2 * ks + khalf;
            uint32_t a[2][4];
#pragma unroll
            for (int mt = 0; mt < 2; mt++) {
                int row = warpM * 32 + mt * 16 + lrow;
                ldmatrix_x4(a[mt], Abase + row * 128 + ((cIdx ^ (row & 7)) << 4));
            }
            uint32_t br[4][4];
#pragma unroll
            for (int j = 0; j < 4; j++) {
                int row = warpN * 64 + j * 16 + lrow;
                ldmatrix_x4(br[j], Bbase + row * 128 + ((cIdx ^ (row & 7)) << 4));
            }
#pragma unroll
            for (int mt = 0; mt < 2; mt++)
#pragma unroll
                for (int j = 0; j < 4; j++) {
                    mma_f16(acc[mt][2 * j],     a[mt], br[j][0], br[j][2]);
                    mma_f16(acc[mt][2 * j + 1], a[mt], br[j][1], br[j][3]);
                }
        }
    }

    // ---- epilogue ----
#pragma unroll
    for (int mt = 0; mt < 2; mt++) {
#pragma unroll
        for (int sub = 0; sub < 2; sub++) {
            const int r = rowBase + warpM * 32 + mt * 16 + g + sub * 8;
#pragma unroll
            for (int nt = 0; nt < 8; nt++) {
                const int c = colBase + warpN * 64 + nt * 8 + 2 * t;
                float2 o;
                o.x = acc[mt][nt][sub * 2 + 0];
                o.y = acc[mt][nt][sub * 2 + 1];
                float2 bi = *(const float2*)&bias[c];
                o.x += bi.x; o.y += bi.y;
                if (res) {
                    float2 rr = *(const float2*)&res[(size_t)r * N + c];
                    o.x += rr.x; o.y += rr.y;
                }
                if (act == 1 || (act == 3 && c < 2 * DM)) {
                    o.x = (o.x > 0.f) ? (o.x + 1.f) : expf(o.x);
                    o.y = (o.y > 0.f) ? (o.y + 1.f) : expf(o.y);
                } else if (act == 2) {
                    o.x = fmaxf(o.x, 0.f);
                    o.y = fmaxf(o.y, 0.f);
                }
                if (act == 3) {
                    int reg = c >> 9;           // 0=q 1=k 2=v
                    int col = c & (DM - 1);
                    __half* hd = (reg == 0) ? Ch : (reg == 1) ? Ch2 : Ch3;
                    *(__half2*)&hd[(size_t)r * DM + col] = __floats2half2_rn(o.x, o.y);
                } else {
                    if (Cf) *(float2*)&Cf[(size_t)r * N + c] = o;
                    if (Ch) *(__half2*)&Ch[(size_t)r * N + c] = __floats2half2_rn(o.x, o.y);
                }
            }
        }
    }
}

// ---------------- pad embeddings: [BS,586] f32 -> [BS,640] fp16 ----------------
__global__ void pad_emb_h(const float* __restrict__ in, __half* __restrict__ out) {
    int i = blockIdx.x * 256 + threadIdx.x;
    if (i >= BS * KPAD) return;
    int r = i / KPAD, c = i - r * KPAD;
    out[i] = (c < F_IN) ? __float2half(in[(size_t)r * F_IN + c]) : __half(0.f);
}

// ---------------- transpose+pad+quantize: f32 in[K,N] -> fp16 out[N,KP] ----------------
__global__ void transpose_pad_h(const float* __restrict__ in, __half* __restrict__ out,
                                int K, int N, int KP) {
    __shared__ float t[32][33];
    int k0 = blockIdx.x * 32, n0 = blockIdx.y * 32;
    int x = threadIdx.x, y = threadIdx.y;
#pragma unroll
    for (int j = 0; j < 32; j += 8) {
        int kk = k0 + y + j;
        t[y + j][x] = (kk < K && n0 + x < N) ? in[(size_t)kk * N + n0 + x] : 0.f;
    }
    __syncthreads();
#pragma unroll
    for (int j = 0; j < 32; j += 8)
        if (n0 + y + j < N && k0 + x < KP)
            out[(size_t)(n0 + y + j) * KP + k0 + x] = __float2half(t[x][y + j]);
}

// ---------------- concat q/k/v biases -> [NLAY,1536] ----------------
__global__ void concat_bias(const float* __restrict__ bq, const float* __restrict__ bk,
                            const float* __restrict__ bv, float* __restrict__ out) {
    int i = blockIdx.x * 256 + threadIdx.x;
    if (i >= NLAY * QKVN) return;
    int l = i / QKVN, c = i - l * QKVN;
    float v;
    if (c < DM)           v = bq[l * DM + c];
    else if (c < 2 * DM)  v = bk[l * DM + c - DM];
    else                  v = bv[l * DM + c - 2 * DM];
    out[i] = v;
}

// ---------------- kv = sum_s k^T v (split-S, fp16 in, fp32 math) ----------------
__global__ __launch_bounds__(256) void kv_kernel(
    const __half* __restrict__ k, const __half* __restrict__ v,
    float* __restrict__ kvpart, float* __restrict__ kspart)
{
    const int bh = blockIdx.x;
    const int b = bh >> 3, h = bh & 7;
    const int chunk = blockIdx.y;
    const int s0 = chunk * KV_CH;
    __shared__ float ksm[64][65];
    __shared__ float vsm[64][64];
    const int tid = threadIdx.x;
    const int m = tid & 63;
    const int dgrp = tid >> 6;
    float acc[16];
#pragma unroll
    for (int i = 0; i < 16; i++) acc[i] = 0.f;
    float kacc = 0.f;

    for (int c = 0; c < KV_CH; c += 64) {
#pragma unroll
        for (int i = 0; i < 8; i++) {
            int idx = tid + i * 256;              // 0..2047 over half2
            int r = idx >> 5, cc = idx & 31;      // 32 half2 per row
            size_t base = (size_t)(b * SEQ + s0 + c + r) * DM + h * HD;
            float2 kf = __half22float2(((const __half2*)(k + base))[cc]);
            float2 vf = __half22float2(((const __half2*)(v + base))[cc]);
            ksm[r][2 * cc] = kf.x; ksm[r][2 * cc + 1] = kf.y;
            vsm[r][2 * cc] = vf.x; vsm[r][2 * cc + 1] = vf.y;
        }
        __syncthreads();
        for (int s = 0; s < 64; s++) {
            float vv = vsm[s][m];
#pragma unroll
            for (int i = 0; i < 16; i++)
                acc[i] = fmaf(ksm[s][dgrp * 16 + i], vv, acc[i]);
        }
        if (tid < 64) {
            float tt = 0.f;
            for (int s = 0; s < 64; s++) tt += ksm[s][tid];
            kacc += tt;
        }
        __syncthreads();
    }
#pragma unroll
    for (int i = 0; i < 16; i++) {
        int d = dgrp * 16 + i;
        kvpart[((size_t)(chunk * BH + bh) * HD + d) * HD + m] = acc[i];
    }
    if (tid < 64) kspart[(size_t)(chunk * BH + bh) * HD + tid] = kacc;
}

__global__ void reduce_kv(const float* __restrict__ part, float* __restrict__ kv) {
    int i = blockIdx.x * 256 + threadIdx.x;
    float a = 0.f;
#pragma unroll
    for (int c = 0; c < NCHUNK; c++) a += part[(size_t)c * (BH * HD * HD) + i];
    kv[i] = a;
}
__global__ void reduce_ks(const float* __restrict__ part, float* __restrict__ ks) {
    int i = blockIdx.x * 256 + threadIdx.x;
    float a = 0.f;
#pragma unroll
    for (int c = 0; c < NCHUNK; c++) a += part[(size_t)c * (BH * HD) + i];
    ks[i] = a;
}

// ---------------- attention apply (fp16 q in, fp16 out) ----------------
__global__ __launch_bounds__(256) void attn_kernel(
    const __half* __restrict__ q, const float* __restrict__ kv,
    const float* __restrict__ ks, __half* __restrict__ out)
{
    const int bh = blockIdx.x;
    const int b = bh >> 3, h = bh & 7;
    const int s0 = blockIdx.y * 64;
    __shared__ float kvsm[64][65];
    __shared__ float qsm[64][65];
    __shared__ float zsm[64];
    __shared__ float kssm[64];
    const int tid = threadIdx.x;
#pragma unroll
    for (int i = 0; i < 8; i++) {
        int idx = tid + i * 256;
        int r = idx >> 5, cc = idx & 31;
        float2 qf = __half22float2(
            ((const __half2*)(q + (size_t)(b * SEQ + s0 + r) * DM + h * HD))[cc]);
        qsm[r][2 * cc] = qf.x; qsm[r][2 * cc + 1] = qf.y;
    }
#pragma unroll
    for (int i = 0; i < 16; i++) {
        int idx = tid + i * 256;
        int d = idx >> 6, m = idx & 63;
        kvsm[d][m] = kv[((size_t)bh * HD + d) * HD + m];
    }
    if (tid < 64) kssm[tid] = ks[bh * HD + tid];
    __syncthreads();
    if (tid < 64) {
        float a = 0.f;
        for (int d = 0; d < 64; d++) a = fmaf(qsm[tid][d], kssm[d], a);
        zsm[tid] = 1.f / (a + EPS_ATTN);
    }
    __syncthreads();
    const int m = tid & 63;
    const int tgrp = tid >> 6;
#pragma unroll
    for (int i = 0; i < 16; i++) {
        int tt = tgrp * 16 + i;
        float a = 0.f;
#pragma unroll
        for (int d = 0; d < 64; d++) a = fmaf(qsm[tt][d], kvsm[d][m], a);
        out[(size_t)(b * SEQ + s0 + tt) * DM + h * HD + m] = __float2half(a * zsm[tt]);
    }
}

// ---------------- block reduce helper ----------------
__device__ __forceinline__ float bsum128(float v, float* sm) {
#pragma unroll
    for (int o = 16; o > 0; o >>= 1) v += __shfl_down_sync(0xffffffffu, v, o);
    int w = threadIdx.x >> 5;
    if ((threadIdx.x & 31) == 0) sm[w] = v;
    __syncthreads();
    float r = sm[0] + sm[1] + sm[2] + sm[3];
    __syncthreads();
    return r;
}

// ---------------- layernorm: f32 out + fp16 copy ----------------
__global__ __launch_bounds__(128) void ln_kernel(
    const float* __restrict__ in, const float* __restrict__ g,
    const float* __restrict__ b, float* __restrict__ out,
    __half* __restrict__ hout)
{
    __shared__ float sm[4];
    const int row = blockIdx.x;
    const int tid = threadIdx.x;
    float4 v = ((const float4*)(in + (size_t)row * DM))[tid];
    float s  = v.x + v.y + v.z + v.w;
    float sq = v.x * v.x + v.y * v.y + v.z * v.z + v.w * v.w;
    s  = bsum128(s, sm);
    sq = bsum128(sq, sm);
    float mu = s * (1.f / DM);
    float var = sq * (1.f / DM) - mu * mu;
    float rstd = rsqrtf(var + EPS_LN);
    float4 gg = ((const float4*)g)[tid];
    float4 bb = ((const float4*)b)[tid];
    float4 o;
    o.x = (v.x - mu) * rstd * gg.x + bb.x;
    o.y = (v.y - mu) * rstd * gg.y + bb.y;
    o.z = (v.z - mu) * rstd * gg.z + bb.z;
    o.w = (v.w - mu) * rstd * gg.w + bb.w;
    ((float4*)(out + (size_t)row * DM))[tid] = o;
    ((__half2*)(hout + (size_t)row * DM))[tid * 2 + 0] = __floats2half2_rn(o.x, o.y);
    ((__half2*)(hout + (size_t)row * DM))[tid * 2 + 1] = __floats2half2_rn(o.z, o.w);
}

// ---------------- fused final LN + out proj ----------------
__global__ __launch_bounds__(128) void final_kernel(
    const float* __restrict__ in, const float* __restrict__ g,
    const float* __restrict__ b, const float* __restrict__ w,
    const float* __restrict__ bout, float* __restrict__ out)
{
    __shared__ float sm[4];
    const int row = blockIdx.x;
    const int tid = threadIdx.x;
    float4 v = ((const float4*)(in + (size_t)row * DM))[tid];
    float s  = v.x + v.y + v.z + v.w;
    float sq = v.x * v.x + v.y * v.y + v.z * v.z + v.w * v.w;
    s  = bsum128(s, sm);
    sq = bsum128(sq, sm);
    float mu = s * (1.f / DM);
    float var = sq * (1.f / DM) - mu * mu;
    float rstd = rsqrtf(var + EPS_LN);
    float4 gg = ((const float4*)g)[tid];
    float4 bb = ((const float4*)b)[tid];
    float4 ww = ((const float4*)w)[tid];
    float acc = ((v.x - mu) * rstd * gg.x + bb.x) * ww.x
              + ((v.y - mu) * rstd * gg.y + bb.y) * ww.y
              + ((v.z - mu) * rstd * gg.z + bb.z) * ww.z
              + ((v.w - mu) * rstd * gg.w + bb.w) * ww.w;
    acc = bsum128(acc, sm);
    if (tid == 0) out[row] = acc + bout[0];
}

// ---------------- launch helpers ----------------
static inline void launch_gemm(const __half* A, const __half* BT, const float* bias,
                               const float* res, float* Cf, __half* Ch,
                               __half* Ch2, __half* Ch3,
                               int M, int N, int K, int act) {
    dim3 grid(N / GBN, M / GBM);
    gemm_h<<<grid, 256, GEMM_SMEM>>>(A, BT, bias, res, Cf, Ch, Ch2, Ch3, M, N, K, act);
}
static inline void launch_transpose(const float* in, __half* out, int K, int N, int KP) {
    dim3 grid((KP + 31) / 32, (N + 31) / 32);
    transpose_pad_h<<<grid, dim3(32, 8)>>>(in, out, K, N, KP);
}

extern "C" void kernel_launch(void* const* d_in, const int* in_sizes, int n_in,
                              void* d_out, int out_size)
{
    const float* emb   = (const float*)d_in[0];
    const float* W0    = (const float*)d_in[1];
    const float* b0    = (const float*)d_in[2];
    const float* Wq    = (const float*)d_in[3];
    const float* bq    = (const float*)d_in[4];
    const float* Wk    = (const float*)d_in[5];
    const float* bk    = (const float*)d_in[6];
    const float* Wv    = (const float*)d_in[7];
    const float* bv    = (const float*)d_in[8];
    const float* Wo    = (const float*)d_in[9];
    const float* bo    = (const float*)d_in[10];
    const float* ln1s  = (const float*)d_in[11];
    const float* ln1b  = (const float*)d_in[12];
    const float* W1    = (const float*)d_in[13];
    const float* b1    = (const float*)d_in[14];
    const float* W2    = (const float*)d_in[15];
    const float* b2    = (const float*)d_in[16];
    const float* ln2s  = (const float*)d_in[17];
    const float* ln2b  = (const float*)d_in[18];
    const float* lnfs  = (const float*)d_in[19];
    const float* lnfb  = (const float*)d_in[20];
    const float* Wout  = (const float*)d_in[21];
    const float* bout  = (const float*)d_in[22];
    float* out = (float*)d_out;

    cudaFuncSetAttribute(gemm_h, cudaFuncAttributeMaxDynamicSharedMemorySize, GEMM_SMEM);

    __half *he, *hx, *hq, *hk, *hv, *ht, *hh;
    __half *w0t, *wqkvt, *wot, *w1t, *w2t;
    float *px, *py, *pkvp, *pksp, *pkv, *pks, *bqkv;
    cudaGetSymbolAddress((void**)&he,  g_he);
    cudaGetSymbolAddress((void**)&hx,  g_hx);
    cudaGetSymbolAddress((void**)&hq,  g_hq);
    cudaGetSymbolAddress((void**)&hk,  g_hk);
    cudaGetSymbolAddress((void**)&hv,  g_hv);
    cudaGetSymbolAddress((void**)&ht,  g_ht);
    cudaGetSymbolAddress((void**)&hh,  g_hh);
    cudaGetSymbolAddress((void**)&px,  g_x);
    cudaGetSymbolAddress((void**)&py,  g_y);
    cudaGetSymbolAddress((void**)&pkvp, g_kvpart);
    cudaGetSymbolAddress((void**)&pksp, g_kspart);
    cudaGetSymbolAddress((void**)&pkv, g_kv);
    cudaGetSymbolAddress((void**)&pks, g_ks);
    cudaGetSymbolAddress((void**)&w0t, g_w0t);
    cudaGetSymbolAddress((void**)&wqkvt, g_wqkvt);
    cudaGetSymbolAddress((void**)&wot, g_wot);
    cudaGetSymbolAddress((void**)&w1t, g_w1t);
    cudaGetSymbolAddress((void**)&w2t, g_w2t);
    cudaGetSymbolAddress((void**)&bqkv, g_bqkv);

    // prep
    pad_emb_h<<<(BS * KPAD + 255) / 256, 256>>>(emb, he);
    launch_transpose(W0, w0t, F_IN, DM, KPAD);
    concat_bias<<<(NLAY * QKVN + 255) / 256, 256>>>(bq, bk, bv, bqkv);
    for (int l = 0; l < NLAY; l++) {
        __half* wl = wqkvt + (size_t)l * QKVN * DM;
        launch_transpose(Wq + (size_t)l * DM * DM, wl,                DM, DM, DM);
        launch_transpose(Wk + (size_t)l * DM * DM, wl + (size_t)DM * DM,     DM, DM, DM);
        launch_transpose(Wv + (size_t)l * DM * DM, wl + (size_t)2 * DM * DM, DM, DM, DM);
        launch_transpose(Wo + (size_t)l * DM * DM, wot + (size_t)l * DM * DM, DM, DM, DM);
        launch_transpose(W1 + (size_t)l * DM * FF, w1t + (size_t)l * DM * FF, DM, FF, DM);
        launch_transpose(W2 + (size_t)l * FF * DM, w2t + (size_t)l * FF * DM, FF, DM, FF);
    }

    // input projection: x0 (f32 + fp16 copy)
    launch_gemm(he, w0t, b0, nullptr, px, hx, nullptr, nullptr, BS, DM, KPAD, 0);

    for (int l = 0; l < NLAY; l++) {
        const __half* wqkv_l = wqkvt + (size_t)l * QKVN * DM;
        const __half* wot_l  = wot + (size_t)l * DM * DM;
        const __half* w1t_l  = w1t + (size_t)l * DM * FF;
        const __half* w2t_l  = w2t + (size_t)l * FF * DM;
        const float* bqkv_l = bqkv + (size_t)l * QKVN;
        const float* bo_l = bo + (size_t)l * DM;
        const float* b1_l = b1 + (size_t)l * FF;
        const float* b2_l = b2 + (size_t)l * DM;

        // fused q/k/v projection -> hq, hk, hv (fp16)
        launch_gemm(hx, wqkv_l, bqkv_l, nullptr, nullptr, hq, hk, hv, BS, QKVN, DM, 3);

        kv_kernel<<<dim3(BH, NCHUNK), 256>>>(hk, hv, pkvp, pksp);
        reduce_kv<<<(BH * HD * HD) / 256, 256>>>(pkvp, pkv);
        reduce_ks<<<(BH * HD) / 256, 256>>>(pksp, pks);
        attn_kernel<<<dim3(BH, SEQ / 64), 256>>>(hq, pkv, pks, ht);

        // out proj + residual -> py; LN -> px + hx
        launch_gemm(ht, wot_l, bo_l, px, py, nullptr, nullptr, nullptr, BS, DM, DM, 0);
        ln_kernel<<<BS, 128>>>(py, ln1s + (size_t)l * DM, ln1b + (size_t)l * DM, px, hx);

        // FFN
        launch_gemm(hx, w1t_l, b1_l, nullptr, nullptr, hh, nullptr, nullptr, BS, FF, DM, 2);
        launch_gemm(hh, w2t_l, b2_l, px, py, nullptr, nullptr, nullptr, BS, DM, FF, 0);
        ln_kernel<<<BS, 128>>>(py, ln2s + (size_t)l * DM, ln2b + (size_t)l * DM, px, hx);
    }

    final_kernel<<<BS, 128>>>(px, lnfs, lnfb, Wout, bout, out);
}

// round 8
// speedup vs baseline: 1.0188x; 1.0188x over previous
#include <cuda_runtime.h>
#include <cuda_fp16.h>
#include <math.h>
#include <stdint.h>

// ---------------- problem constants ----------------
#define BATCH 8
#define SEQ   4096
#define F_IN  586
#define KPAD  640            // F_IN padded to multiple of 64
#define DM    512
#define NH    8
#define HD    64
#define FF    1024
#define NLAY  2
#define BS    (BATCH*SEQ) // 32768
#define BH    (BATCH*NH)  // 64
#define QKVN  (3*DM)      // 1536
#define EPS_ATTN 1e-6f
#define EPS_LN   1e-5f

// ---------------- scratch (device globals) ----------------
__device__ __half g_he[BS*KPAD];     // fp16 padded embeddings
__device__ __half g_hx[BS*DM];       // fp16 copy of x (GEMM A operand)
__device__ __half g_hq[BS*DM];       // fp16 q
__device__ __half g_hk[BS*DM];       // fp16 k
__device__ __half g_hv[BS*DM];       // fp16 v
__device__ __half g_ht[BS*DM];       // fp16 attention output
__device__ __half g_hh[BS*FF];       // fp16 FFN hidden
__device__ float  g_x [BS*DM];       // f32 x (residual / LN)
__device__ float  g_y [BS*DM];       // f32 gemm out (pre-LN)
#define NCHUNK 8
#define KV_CH  (SEQ/NCHUNK)
__device__ float g_kvpart[NCHUNK*BH*HD*HD];
__device__ float g_kspart[NCHUNK*BH*HD];
__device__ float g_kv[BH*HD*HD];
__device__ float g_ks[BH*HD];
// fp16 transposed weights [N,K]
__device__ __half g_w0t [DM*KPAD];
__device__ __half g_wqkvt[NLAY*QKVN*DM];
__device__ __half g_wot [NLAY*DM*DM];
__device__ __half g_w1t [NLAY*FF*DM];
__device__ __half g_w2t [NLAY*DM*FF];
__device__ float  g_bqkv[NLAY*QKVN];

// ---------------- helpers ----------------
__device__ __forceinline__ uint32_t smem_u32(const void* p) {
    uint32_t a;
    asm("{ .reg .u64 t; cvta.to.shared.u64 t, %1; cvt.u32.u64 %0, t; }" : "=r"(a) : "l"(p));
    return a;
}
__device__ __forceinline__ void cp_async16(uint32_t dst, const void* src) {
    asm volatile("cp.async.cg.shared.global [%0], [%1], 16;"
                 :: "r"(dst), "l"(src) : "memory");
}
#define CP_COMMIT() asm volatile("cp.async.commit_group;" ::: "memory")

__device__ __forceinline__ void ldmatrix_x4(uint32_t* r, uint32_t addr) {
    asm volatile("ldmatrix.sync.aligned.m8n8.x4.shared.b16 {%0,%1,%2,%3}, [%4];"
                 : "=r"(r[0]), "=r"(r[1]), "=r"(r[2]), "=r"(r[3]) : "r"(addr));
}
__device__ __forceinline__ void mma_f16(float* c, const uint32_t* a, uint32_t b0, uint32_t b1) {
    asm volatile(
        "mma.sync.aligned.m16n8k16.row.col.f32.f16.f16.f32 "
        "{%0,%1,%2,%3}, {%4,%5,%6,%7}, {%8,%9}, {%0,%1,%2,%3};"
        : "+f"(c[0]), "+f"(c[1]), "+f"(c[2]), "+f"(c[3])
        : "r"(a[0]), "r"(a[1]), "r"(a[2]), "r"(a[3]), "r"(b0), "r"(b1));
}

// ---------------- fp16 tensor-core GEMM (2-stage, 64 KB smem) ----------------
// act: 0 none, 1 elu+1, 2 relu, 3 qkv-mode (elu+1 for c<1024; fp16 out split
// across Ch/Ch2/Ch3 each [M,512]).
#define GBM 128
#define GBN 128
#define HBK 64
#define TILE_B 16384
#define GEMM_SMEM (4*TILE_B)          // 64 KB

__global__ __launch_bounds__(256) void gemm_h(
    const __half* __restrict__ A, const __half* __restrict__ BT,
    const float* __restrict__ bias, const float* __restrict__ res,
    float* __restrict__ Cf, __half* __restrict__ Ch,
    __half* __restrict__ Ch2, __half* __restrict__ Ch3,
    int M, int N, int K, int act)
{
    extern __shared__ char smraw[];
    const uint32_t smBase = smem_u32(smraw);
    const int tid  = threadIdx.x;
    const int warp = tid >> 5;
    const int lane = tid & 31;
    const int g = lane >> 2;
    const int t = lane & 3;
    const int warpM = warp & 3;
    const int warpN = warp >> 2;
    const int rowBase = blockIdx.y * GBM;
    const int colBase = blockIdx.x * GBN;
    const int kiters = K / HBK;

    auto loadTile = [&](int it, int buf) {
        const int k0 = it * HBK;
#pragma unroll
        for (int p = 0; p < 4; p++) {
            int idx = tid + p * 256;
            int row = idx >> 3, c = idx & 7;
            uint32_t dst = smBase + buf * TILE_B + row * 128 + ((c ^ (row & 7)) << 4);
            cp_async16(dst, &A[(size_t)(rowBase + row) * K + k0 + c * 8]);
        }
#pragma unroll
        for (int p = 0; p < 4; p++) {
            int idx = tid + p * 256;
            int row = idx >> 3, c = idx & 7;
            uint32_t dst = smBase + 2 * TILE_B + buf * TILE_B + row * 128 + ((c ^ (row & 7)) << 4);
            cp_async16(dst, &BT[(size_t)(colBase + row) * K + k0 + c * 8]);
        }
    };

    float acc[2][8][4];
#pragma unroll
    for (int mt = 0; mt < 2; mt++)
#pragma unroll
        for (int nt = 0; nt < 8; nt++)
#pragma unroll
            for (int i = 0; i < 4; i++) acc[mt][nt][i] = 0.f;

    loadTile(0, 0);
    CP_COMMIT();

    const int lrow = lane & 15;
    const int khalf = lane >> 4;

    for (int it = 0; it < kiters; ++it) {
        const int buf = it & 1;
        if (it + 1 < kiters) {
            loadTile(it + 1, buf ^ 1);
            CP_COMMIT();
            asm volatile("cp.async.wait_group 1;" ::: "memory");
        } else {
            asm volatile("cp.async.wait_group 0;" ::: "memory");
        }
        __syncthreads();

        const uint32_t Abase = smBase + buf * TILE_B;
        const uint32_t Bbase = smBase + 2 * TILE_B + buf * TILE_B;
#pragma unroll
        for (int ks = 0; ks < 4; ks++) {
            const int cIdx = 2 * ks + khalf;
            uint32_t a[2][4];
#pragma unroll
            for (int mt = 0; mt < 2; mt++) {
                int row = warpM * 32 + mt * 16 + lrow;
                ldmatrix_x4(a[mt], Abase + row * 128 + ((cIdx ^ (row & 7)) << 4));
            }
            uint32_t br[4][4];
#pragma unroll
            for (int j = 0; j < 4; j++) {
                int row = warpN * 64 + j * 16 + lrow;
                ldmatrix_x4(br[j], Bbase + row * 128 + ((cIdx ^ (row & 7)) << 4));
            }
#pragma unroll
            for (int mt = 0; mt < 2; mt++)
#pragma unroll
                for (int j = 0; j < 4; j++) {
                    mma_f16(acc[mt][2 * j],     a[mt], br[j][0], br[j][2]);
                    mma_f16(acc[mt][2 * j + 1], a[mt], br[j][1], br[j][3]);
                }
        }
        __syncthreads();
    }

    // ---- epilogue ----
#pragma unroll
    for (int mt = 0; mt < 2; mt++) {
#pragma unroll
        for (int sub = 0; sub < 2; sub++) {
            const int r = rowBase + warpM * 32 + mt * 16 + g + sub * 8;
#pragma unroll
            for (int nt = 0; nt < 8; nt++) {
                const int c = colBase + warpN * 64 + nt * 8 + 2 * t;
                float2 o;
                o.x = acc[mt][nt][sub * 2 + 0];
                o.y = acc[mt][nt][sub * 2 + 1];
                float2 bi = *(const float2*)&bias[c];
                o.x += bi.x; o.y += bi.y;
                if (res) {
                    float2 rr = *(const float2*)&res[(size_t)r * N + c];
                    o.x += rr.x; o.y += rr.y;
                }
                if (act == 1 || (act == 3 && c < 2 * DM)) {
                    o.x = (o.x > 0.f) ? (o.x + 1.f) : expf(o.x);
                    o.y = (o.y > 0.f) ? (o.y + 1.f) : expf(o.y);
                } else if (act == 2) {
                    o.x = fmaxf(o.x, 0.f);
                    o.y = fmaxf(o.y, 0.f);
                }
                if (act == 3) {
                    int reg = c >> 9;           // 0=q 1=k 2=v (uniform per CTA)
                    int col = c & (DM - 1);
                    __half* hd = (reg == 0) ? Ch : (reg == 1) ? Ch2 : Ch3;
                    *(__half2*)&hd[(size_t)r * DM + col] = __floats2half2_rn(o.x, o.y);
                } else {
                    if (Cf) *(float2*)&Cf[(size_t)r * N + c] = o;
                    if (Ch) *(__half2*)&Ch[(size_t)r * N + c] = __floats2half2_rn(o.x, o.y);
                }
            }
        }
    }
}

// ---------------- pad embeddings: [BS,586] f32 -> [BS,640] fp16 ----------------
__global__ void pad_emb_h(const float* __restrict__ in, __half* __restrict__ out) {
    int i = blockIdx.x * 256 + threadIdx.x;
    if (i >= BS * KPAD) return;
    int r = i / KPAD, c = i - r * KPAD;
    out[i] = (c < F_IN) ? __float2half(in[(size_t)r * F_IN + c]) : __half(0.f);
}

// ---------------- batched transpose+pad+quantize: f32 [K,N] -> fp16 [N,KP] ----------------
#define NTR 13
struct TrDesc { const float* in; __half* out; int K; int N; int KP; int tileStart; };
struct TrPack { TrDesc d[NTR]; };

__global__ void transpose_batch(TrPack p) {
    __shared__ float t[32][33];
    const int bt = blockIdx.x;
    int mi = 0;
#pragma unroll
    for (int i = 1; i < NTR; i++)
        if (bt >= p.d[i].tileStart) mi = i;
    const TrDesc de = p.d[mi];
    const int lt = bt - de.tileStart;
    const int ktiles = de.KP >> 5;
    const int k0 = (lt % ktiles) * 32;
    const int n0 = (lt / ktiles) * 32;
    const int x = threadIdx.x, y = threadIdx.y;
#pragma unroll
    for (int j = 0; j < 32; j += 8) {
        int kk = k0 + y + j;
        t[y + j][x] = (kk < de.K && n0 + x < de.N)
                      ? de.in[(size_t)kk * de.N + n0 + x] : 0.f;
    }
    __syncthreads();
#pragma unroll
    for (int j = 0; j < 32; j += 8)
        if (n0 + y + j < de.N)
            de.out[(size_t)(n0 + y + j) * de.KP + k0 + x] = __float2half(t[x][y + j]);
}

// ---------------- concat q/k/v biases -> [NLAY,1536] ----------------
__global__ void concat_bias(const float* __restrict__ bq, const float* __restrict__ bk,
                            const float* __restrict__ bv, float* __restrict__ out) {
    int i = blockIdx.x * 256 + threadIdx.x;
    if (i >= NLAY * QKVN) return;
    int l = i / QKVN, c = i - l * QKVN;
    float v;
    if (c < DM)           v = bq[l * DM + c];
    else if (c < 2 * DM)  v = bk[l * DM + c - DM];
    else                  v = bv[l * DM + c - 2 * DM];
    out[i] = v;
}

// ---------------- kv = sum_s k^T v (split-S, fp16 in, fp32 math) ----------------
__global__ __launch_bounds__(256) void kv_kernel(
    const __half* __restrict__ k, const __half* __restrict__ v,
    float* __restrict__ kvpart, float* __restrict__ kspart)
{
    const int bh = blockIdx.x;
    const int b = bh >> 3, h = bh & 7;
    const int chunk = blockIdx.y;
    const int s0 = chunk * KV_CH;
    __shared__ float ksm[64][65];
    __shared__ float vsm[64][64];
    const int tid = threadIdx.x;
    const int m = tid & 63;
    const int dgrp = tid >> 6;
    float acc[16];
#pragma unroll
    for (int i = 0; i < 16; i++) acc[i] = 0.f;
    float kacc = 0.f;

    for (int c = 0; c < KV_CH; c += 64) {
#pragma unroll
        for (int i = 0; i < 8; i++) {
            int idx = tid + i * 256;
            int r = idx >> 5, cc = idx & 31;
            size_t base = (size_t)(b * SEQ + s0 + c + r) * DM + h * HD;
            float2 kf = __half22float2(((const __half2*)(k + base))[cc]);
            float2 vf = __half22float2(((const __half2*)(v + base))[cc]);
            ksm[r][2 * cc] = kf.x; ksm[r][2 * cc + 1] = kf.y;
            vsm[r][2 * cc] = vf.x; vsm[r][2 * cc + 1] = vf.y;
        }
        __syncthreads();
        for (int s = 0; s < 64; s++) {
            float vv = vsm[s][m];
#pragma unroll
            for (int i = 0; i < 16; i++)
                acc[i] = fmaf(ksm[s][dgrp * 16 + i], vv, acc[i]);
        }
        if (tid < 64) {
            float tt = 0.f;
            for (int s = 0; s < 64; s++) tt += ksm[s][tid];
            kacc += tt;
        }
        __syncthreads();
    }
#pragma unroll
    for (int i = 0; i < 16; i++) {
        int d = dgrp * 16 + i;
        kvpart[((size_t)(chunk * BH + bh) * HD + d) * HD + m] = acc[i];
    }
    if (tid < 64) kspart[(size_t)(chunk * BH + bh) * HD + tid] = kacc;
}

__global__ void reduce_kv(const float* __restrict__ part, float* __restrict__ kv) {
    int i = blockIdx.x * 256 + threadIdx.x;
    float a = 0.f;
#pragma unroll
    for (int c = 0; c < NCHUNK; c++) a += part[(size_t)c * (BH * HD * HD) + i];
    kv[i] = a;
}
__global__ void reduce_ks(const float* __restrict__ part, float* __restrict__ ks) {
    int i = blockIdx.x * 256 + threadIdx.x;
    float a = 0.f;
#pragma unroll
    for (int c = 0; c < NCHUNK; c++) a += part[(size_t)c * (BH * HD) + i];
    ks[i] = a;
}

// ---------------- attention apply (fp16 q in, fp16 out) ----------------
__global__ __launch_bounds__(256) void attn_kernel(
    const __half* __restrict__ q, const float* __restrict__ kv,
    const float* __restrict__ ks, __half* __restrict__ out)
{
    const int bh = blockIdx.x;
    const int b = bh >> 3, h = bh & 7;
    const int s0 = blockIdx.y * 64;
    __shared__ float kvsm[64][65];
    __shared__ float qsm[64][65];
    __shared__ float zsm[64];
    __shared__ float kssm[64];
    const int tid = threadIdx.x;
#pragma unroll
    for (int i = 0; i < 8; i++) {
        int idx = tid + i * 256;
        int r = idx >> 5, cc = idx & 31;
        float2 qf = __half22float2(
            ((const __half2*)(q + (size_t)(b * SEQ + s0 + r) * DM + h * HD))[cc]);
        qsm[r][2 * cc] = qf.x; qsm[r][2 * cc + 1] = qf.y;
    }
#pragma unroll
    for (int i = 0; i < 16; i++) {
        int idx = tid + i * 256;
        int d = idx >> 6, m = idx & 63;
        kvsm[d][m] = kv[((size_t)bh * HD + d) * HD + m];
    }
    if (tid < 64) kssm[tid] = ks[bh * HD + tid];
    __syncthreads();
    if (tid < 64) {
        float a = 0.f;
        for (int d = 0; d < 64; d++) a = fmaf(qsm[tid][d], kssm[d], a);
        zsm[tid] = 1.f / (a + EPS_ATTN);
    }
    __syncthreads();
    const int m = tid & 63;
    const int tgrp = tid >> 6;
#pragma unroll
    for (int i = 0; i < 16; i++) {
        int tt = tgrp * 16 + i;
        float a = 0.f;
#pragma unroll
        for (int d = 0; d < 64; d++) a = fmaf(qsm[tt][d], kvsm[d][m], a);
        out[(size_t)(b * SEQ + s0 + tt) * DM + h * HD + m] = __float2half(a * zsm[tt]);
    }
}

// ---------------- block reduce helper ----------------
__device__ __forceinline__ float bsum128(float v, float* sm) {
#pragma unroll
    for (int o = 16; o > 0; o >>= 1) v += __shfl_down_sync(0xffffffffu, v, o);
    int w = threadIdx.x >> 5;
    if ((threadIdx.x & 31) == 0) sm[w] = v;
    __syncthreads();
    float r = sm[0] + sm[1] + sm[2] + sm[3];
    __syncthreads();
    return r;
}

// ---------------- layernorm: f32 out + fp16 copy ----------------
__global__ __launch_bounds__(128) void ln_kernel(
    const float* __restrict__ in, const float* __restrict__ g,
    const float* __restrict__ b, float* __restrict__ out,
    __half* __restrict__ hout)
{
    __shared__ float sm[4];
    const int row = blockIdx.x;
    const int tid = threadIdx.x;
    float4 v = ((const float4*)(in + (size_t)row * DM))[tid];
    float s  = v.x + v.y + v.z + v.w;
    float sq = v.x * v.x + v.y * v.y + v.z * v.z + v.w * v.w;
    s  = bsum128(s, sm);
    sq = bsum128(sq, sm);
    float mu = s * (1.f / DM);
    float var = sq * (1.f / DM) - mu * mu;
    float rstd = rsqrtf(var + EPS_LN);
    float4 gg = ((const float4*)g)[tid];
    float4 bb = ((const float4*)b)[tid];
    float4 o;
    o.x = (v.x - mu) * rstd * gg.x + bb.x;
    o.y = (v.y - mu) * rstd * gg.y + bb.y;
    o.z = (v.z - mu) * rstd * gg.z + bb.z;
    o.w = (v.w - mu) * rstd * gg.w + bb.w;
    ((float4*)(out + (size_t)row * DM))[tid] = o;
    ((__half2*)(hout + (size_t)row * DM))[tid * 2 + 0] = __floats2half2_rn(o.x, o.y);
    ((__half2*)(hout + (size_t)row * DM))[tid * 2 + 1] = __floats2half2_rn(o.z, o.w);
}

// ---------------- fused final LN + out proj ----------------
__global__ __launch_bounds__(128) void final_kernel(
    const float* __restrict__ in, const float* __restrict__ g,
    const float* __restrict__ b, const float* __restrict__ w,
    const float* __restrict__ bout, float* __restrict__ out)
{
    __shared__ float sm[4];
    const int row = blockIdx.x;
    const int tid = threadIdx.x;
    float4 v = ((const float4*)(in + (size_t)row * DM))[tid];
    float s  = v.x + v.y + v.z + v.w;
    float sq = v.x * v.x + v.y * v.y + v.z * v.z + v.w * v.w;
    s  = bsum128(s, sm);
    sq = bsum128(sq, sm);
    float mu = s * (1.f / DM);
    float var = sq * (1.f / DM) - mu * mu;
    float rstd = rsqrtf(var + EPS_LN);
    float4 gg = ((const float4*)g)[tid];
    float4 bb = ((const float4*)b)[tid];
    float4 ww = ((const float4*)w)[tid];
    float acc = ((v.x - mu) * rstd * gg.x + bb.x) * ww.x
              + ((v.y - mu) * rstd * gg.y + bb.y) * ww.y
              + ((v.z - mu) * rstd * gg.z + bb.z) * ww.z
              + ((v.w - mu) * rstd * gg.w + bb.w) * ww.w;
    acc = bsum128(acc, sm);
    if (tid == 0) out[row] = acc + bout[0];
}

// ---------------- launch helpers ----------------
static inline void launch_gemm(const __half* A, const __half* BT, const float* bias,
                               const float* res, float* Cf, __half* Ch,
                               __half* Ch2, __half* Ch3,
                               int M, int N, int K, int act) {
    dim3 grid(N / GBN, M / GBM);
    gemm_h<<<grid, 256, GEMM_SMEM>>>(A, BT, bias, res, Cf, Ch, Ch2, Ch3, M, N, K, act);
}

extern "C" void kernel_launch(void* const* d_in, const int* in_sizes, int n_in,
                              void* d_out, int out_size)
{
    const float* emb   = (const float*)d_in[0];
    const float* W0    = (const float*)d_in[1];
    const float* b0    = (const float*)d_in[2];
    const float* Wq    = (const float*)d_in[3];
    const float* bq    = (const float*)d_in[4];
    const float* Wk    = (const float*)d_in[5];
    const float* bk    = (const float*)d_in[6];
    const float* Wv    = (const float*)d_in[7];
    const float* bv    = (const float*)d_in[8];
    const float* Wo    = (const float*)d_in[9];
    const float* bo    = (const float*)d_in[10];
    const float* ln1s  = (const float*)d_in[11];
    const float* ln1b  = (const float*)d_in[12];
    const float* W1    = (const float*)d_in[13];
    const float* b1    = (const float*)d_in[14];
    const float* W2    = (const float*)d_in[15];
    const float* b2    = (const float*)d_in[16];
    const float* ln2s  = (const float*)d_in[17];
    const float* ln2b  = (const float*)d_in[18];
    const float* lnfs  = (const float*)d_in[19];
    const float* lnfb  = (const float*)d_in[20];
    const float* Wout  = (const float*)d_in[21];
    const float* bout  = (const float*)d_in[22];
    float* out = (float*)d_out;

    cudaFuncSetAttribute(gemm_h, cudaFuncAttributeMaxDynamicSharedMemorySize, GEMM_SMEM);

    __half *he, *hx, *hq, *hk, *hv, *ht, *hh;
    __half *w0t, *wqkvt, *wot, *w1t, *w2t;
    float *px, *py, *pkvp, *pksp, *pkv, *pks, *bqkv;
    cudaGetSymbolAddress((void**)&he,  g_he);
    cudaGetSymbolAddress((void**)&hx,  g_hx);
    cudaGetSymbolAddress((void**)&hq,  g_hq);
    cudaGetSymbolAddress((void**)&hk,  g_hk);
    cudaGetSymbolAddress((void**)&hv,  g_hv);
    cudaGetSymbolAddress((void**)&ht,  g_ht);
    cudaGetSymbolAddress((void**)&hh,  g_hh);
    cudaGetSymbolAddress((void**)&px,  g_x);
    cudaGetSymbolAddress((void**)&py,  g_y);
    cudaGetSymbolAddress((void**)&pkvp, g_kvpart);
    cudaGetSymbolAddress((void**)&pksp, g_kspart);
    cudaGetSymbolAddress((void**)&pkv, g_kv);
    cudaGetSymbolAddress((void**)&pks, g_ks);
    cudaGetSymbolAddress((void**)&w0t, g_w0t);
    cudaGetSymbolAddress((void**)&wqkvt, g_wqkvt);
    cudaGetSymbolAddress((void**)&wot, g_wot);
    cudaGetSymbolAddress((void**)&w1t, g_w1t);
    cudaGetSymbolAddress((void**)&w2t, g_w2t);
    cudaGetSymbolAddress((void**)&bqkv, g_bqkv);

    // ---- prep: pad embeddings + batched weight transpose + bias concat ----
    pad_emb_h<<<(BS * KPAD + 255) / 256, 256>>>(emb, he);
    concat_bias<<<(NLAY * QKVN + 255) / 256, 256>>>(bq, bk, bv, bqkv);

    TrPack pack;
    int tileOff = 0;
    auto addTr = [&](int idx, const float* in, __half* outp, int K, int N, int KP) {
        pack.d[idx].in = in; pack.d[idx].out = outp;
        pack.d[idx].K = K; pack.d[idx].N = N; pack.d[idx].KP = KP;
        pack.d[idx].tileStart = tileOff;
        tileOff += (KP / 32) * ((N + 31) / 32);
    };
    int di = 0;
    addTr(di++, W0, w0t, F_IN, DM, KPAD);
    for (int l = 0; l < NLAY; l++) {
        __half* wl = wqkvt + (size_t)l * QKVN * DM;
        addTr(di++, Wq + (size_t)l * DM * DM, wl,                        DM, DM, DM);
        addTr(di++, Wk + (size_t)l * DM * DM, wl + (size_t)DM * DM,      DM, DM, DM);
        addTr(di++, Wv + (size_t)l * DM * DM, wl + (size_t)2 * DM * DM,  DM, DM, DM);
        addTr(di++, Wo + (size_t)l * DM * DM, wot + (size_t)l * DM * DM, DM, DM, DM);
        addTr(di++, W1 + (size_t)l * DM * FF, w1t + (size_t)l * DM * FF, DM, FF, DM);
        addTr(di++, W2 + (size_t)l * FF * DM, w2t + (size_t)l * FF * DM, FF, DM, FF);
    }
    transpose_batch<<<tileOff, dim3(32, 8)>>>(pack);

    // ---- input projection: x0 (f32 + fp16 copy) ----
    launch_gemm(he, w0t, b0, nullptr, px, hx, nullptr, nullptr, BS, DM, KPAD, 0);

    for (int l = 0; l < NLAY; l++) {
        const __half* wqkv_l = wqkvt + (size_t)l * QKVN * DM;
        const __half* wot_l  = wot + (size_t)l * DM * DM;
        const __half* w1t_l  = w1t + (size_t)l * DM * FF;
        const __half* w2t_l  = w2t + (size_t)l * FF * DM;
        const float* bqkv_l = bqkv + (size_t)l * QKVN;
        const float* bo_l = bo + (size_t)l * DM;
        const float* b1_l = b1 + (size_t)l * FF;
        const float* b2_l = b2 + (size_t)l * DM;

        // fused q/k/v projection -> hq, hk, hv (fp16)
        launch_gemm(hx, wqkv_l, bqkv_l, nullptr, nullptr, hq, hk, hv, BS, QKVN, DM, 3);

        kv_kernel<<<dim3(BH, NCHUNK), 256>>>(hk, hv, pkvp, pksp);
        reduce_kv<<<(BH * HD * HD) / 256, 256>>>(pkvp, pkv);
        reduce_ks<<<(BH * HD) / 256, 256>>>(pksp, pks);
        attn_kernel<<<dim3(BH, SEQ / 64), 256>>>(hq, pkv, pks, ht);

        // out proj + residual -> py; LN -> px + hx
        launch_gemm(ht, wot_l, bo_l, px, py, nullptr, nullptr, nullptr, BS, DM, DM, 0);
        ln_kernel<<<BS, 128>>>(py, ln1s + (size_t)l * DM, ln1b + (size_t)l * DM, px, hx);

        // FFN
        launch_gemm(hx, w1t_l, b1_l, nullptr, nullptr, hh, nullptr, nullptr, BS, FF, DM, 2);
        launch_gemm(hh, w2t_l, b2_l, px, py, nullptr, nullptr, nullptr, BS, DM, FF, 0);
        ln_kernel<<<BS, 128>>>(py, ln2s + (size_t)l * DM, ln2b + (size_t)l * DM, px, hx);
    }

    final_kernel<<<BS, 128>>>(px, lnfs, lnfb, Wout, bout, out);
}

// round 9
// speedup vs baseline: 1.1248x; 1.1040x over previous
#include <cuda_runtime.h>
#include <cuda_fp16.h>
#include <math.h>
#include <stdint.h>

// ---------------- problem constants ----------------
#define BATCH 8
#define SEQ   4096
#define F_IN  586
#define KPAD  640
#define DM    512
#define NH    8
#define HD    64
#define FF    1024
#define NLAY  2
#define BS    (BATCH*SEQ)
#define BH    (BATCH*NH)
#define QKVN  (3*DM)
#define EPS_ATTN 1e-6f
#define EPS_LN   1e-5f

// ---------------- scratch ----------------
__device__ __half g_he[BS*KPAD];
__device__ __half g_hx[BS*DM];
__device__ __half g_hq[BS*DM];
__device__ __half g_hk[BS*DM];
__device__ __half g_hv[BS*DM];
__device__ __half g_ht[BS*DM];
__device__ __half g_hh[BS*FF];
__device__ float  g_x [BS*DM];
__device__ float  g_y [BS*DM];
#define NCHUNK 8
#define KV_CH  (SEQ/NCHUNK)
__device__ float g_kvpart[NCHUNK*BH*HD*HD];
__device__ float g_kspart[NCHUNK*BH*HD];
__device__ float g_kv[BH*HD*HD];
__device__ float g_ks[BH*HD];
__device__ __half g_w0t [DM*KPAD];
__device__ __half g_wqkvt[NLAY*QKVN*DM];
__device__ __half g_wot [NLAY*DM*DM];
__device__ __half g_w1t [NLAY*FF*DM];
__device__ __half g_w2t [NLAY*DM*FF];
__device__ float  g_bqkv[NLAY*QKVN];

// ---------------- helpers ----------------
__device__ __forceinline__ uint32_t smem_u32(const void* p) {
    uint32_t a;
    asm("{ .reg .u64 t; cvta.to.shared.u64 t, %1; cvt.u32.u64 %0, t; }" : "=r"(a) : "l"(p));
    return a;
}
__device__ __forceinline__ void cp_async16(uint32_t dst, const void* src) {
    asm volatile("cp.async.cg.shared.global [%0], [%1], 16;"
                 :: "r"(dst), "l"(src) : "memory");
}
#define CP_COMMIT() asm volatile("cp.async.commit_group;" ::: "memory")
#define CP_WAIT0()  asm volatile("cp.async.wait_group 0;" ::: "memory")

__device__ __forceinline__ void ldmatrix_x4(uint32_t* r, uint32_t addr) {
    asm volatile("ldmatrix.sync.aligned.m8n8.x4.shared.b16 {%0,%1,%2,%3}, [%4];"
                 : "=r"(r[0]), "=r"(r[1]), "=r"(r[2]), "=r"(r[3]) : "r"(addr));
}
__device__ __forceinline__ void mma_f16(float* c, const uint32_t* a, uint32_t b0, uint32_t b1) {
    asm volatile(
        "mma.sync.aligned.m16n8k16.row.col.f32.f16.f16.f32 "
        "{%0,%1,%2,%3}, {%4,%5,%6,%7}, {%8,%9}, {%0,%1,%2,%3};"
        : "+f"(c[0]), "+f"(c[1]), "+f"(c[2]), "+f"(c[3])
        : "r"(a[0]), "r"(a[1]), "r"(a[2]), "r"(a[3]), "r"(b0), "r"(b1));
}

// ---------------- templated fp16 tensor-core GEMM ----------------
// OM: 0 = f32 only, 1 = fp16 only, 2 = f32 + fp16, 3 = qkv split (3x fp16 [M,512])
// ACT: 0 none, 1 elu+1, 2 relu, 3 qkv (elu+1 for c < 1024)
#define GBM 128
#define GBN 128
#define TILE_B 16384
#define GEMM_SMEM (4*TILE_B)

template<int KITERS, int N, int ACT, bool HAS_RES, int OM>
__global__ __launch_bounds__(256) void gemm_t(
    const __half* __restrict__ A, const __half* __restrict__ BT,
    const float* __restrict__ bias, const float* __restrict__ res,
    float* __restrict__ Cf, __half* __restrict__ Ch,
    __half* __restrict__ Ch2, __half* __restrict__ Ch3)
{
    constexpr int K = KITERS * 64;
    extern __shared__ char smraw[];
    const uint32_t smBase = smem_u32(smraw);
    const int tid  = threadIdx.x;
    const int warp = tid >> 5;
    const int lane = tid & 31;
    const int g = lane >> 2;
    const int t = lane & 3;
    const int warpM = warp & 3;
    const int warpN = warp >> 2;
    const int rowBase = blockIdx.y * GBM;
    const int colBase = blockIdx.x * GBN;

    const int ldr = tid >> 3;          // 0..31
    const int ldc = tid & 7;           // 0..7
    auto loadTile = [&](int it, int buf) {
        const int k0 = it * 64;
#pragma unroll
        for (int p = 0; p < 4; p++) {
            int row = p * 32 + ldr;
            uint32_t dst = smBase + buf * TILE_B + row * 128 + ((ldc ^ (row & 7)) << 4);
            cp_async16(dst, &A[(size_t)(rowBase + row) * K + k0 + ldc * 8]);
        }
#pragma unroll
        for (int p = 0; p < 4; p++) {
            int row = p * 32 + ldr;
            uint32_t dst = smBase + 2 * TILE_B + buf * TILE_B + row * 128 + ((ldc ^ (row & 7)) << 4);
            cp_async16(dst, &BT[(size_t)(colBase + row) * K + k0 + ldc * 8]);
        }
    };

    float acc[2][8][4];
#pragma unroll
    for (int mt = 0; mt < 2; mt++)
#pragma unroll
        for (int nt = 0; nt < 8; nt++)
#pragma unroll
            for (int i = 0; i < 4; i++) acc[mt][nt][i] = 0.f;

    loadTile(0, 0);
    CP_COMMIT();

    const int lrow = lane & 15;
    const int khalf = lane >> 4;

#pragma unroll 1
    for (int it = 0; it < KITERS; ++it) {
        const int buf = it & 1;
        CP_WAIT0();              // tile `it` landed
        __syncthreads();         // all warps done with buf^1 (iter it-1)
        if (it + 1 < KITERS) {
            loadTile(it + 1, buf ^ 1);
            CP_COMMIT();
        }
        const uint32_t Abase = smBase + buf * TILE_B;
        const uint32_t Bbase = smBase + 2 * TILE_B + buf * TILE_B;
#pragma unroll
        for (int ks = 0; ks < 4; ks++) {
            const int cIdx = 2 * ks + khalf;
            uint32_t a[2][4];
#pragma unroll
            for (int mt = 0; mt < 2; mt++) {
                int row = warpM * 32 + mt * 16 + lrow;
                ldmatrix_x4(a[mt], Abase + row * 128 + ((cIdx ^ (row & 7)) << 4));
            }
            uint32_t br[4][4];
#pragma unroll
            for (int j = 0; j < 4; j++) {
                int row = warpN * 64 + j * 16 + lrow;
                ldmatrix_x4(br[j], Bbase + row * 128 + ((cIdx ^ (row & 7)) << 4));
            }
#pragma unroll
            for (int mt = 0; mt < 2; mt++)
#pragma unroll
                for (int j = 0; j < 4; j++) {
                    mma_f16(acc[mt][2 * j],     a[mt], br[j][0], br[j][2]);
                    mma_f16(acc[mt][2 * j + 1], a[mt], br[j][1], br[j][3]);
                }
        }
    }

    // ---- epilogue ----
#pragma unroll
    for (int mt = 0; mt < 2; mt++) {
#pragma unroll
        for (int sub = 0; sub < 2; sub++) {
            const int r = rowBase + warpM * 32 + mt * 16 + g + sub * 8;
#pragma unroll
            for (int nt = 0; nt < 8; nt++) {
                const int c = colBase + warpN * 64 + nt * 8 + 2 * t;
                float2 o;
                o.x = acc[mt][nt][sub * 2 + 0];
                o.y = acc[mt][nt][sub * 2 + 1];
                float2 bi = *(const float2*)&bias[c];
                o.x += bi.x; o.y += bi.y;
                if (HAS_RES) {
                    float2 rr = *(const float2*)&res[(size_t)r * N + c];
                    o.x += rr.x; o.y += rr.y;
                }
                if (ACT == 1 || (ACT == 3 && c < 2 * DM)) {
                    o.x = (o.x > 0.f) ? (o.x + 1.f) : expf(o.x);
                    o.y = (o.y > 0.f) ? (o.y + 1.f) : expf(o.y);
                } else if (ACT == 2) {
                    o.x = fmaxf(o.x, 0.f);
                    o.y = fmaxf(o.y, 0.f);
                }
                if (OM == 3) {
                    int reg = c >> 9;
                    int col = c & (DM - 1);
                    __half* hd = (reg == 0) ? Ch : (reg == 1) ? Ch2 : Ch3;
                    *(__half2*)&hd[(size_t)r * DM + col] = __floats2half2_rn(o.x, o.y);
                } else {
                    if (OM == 0 || OM == 2)
                        *(float2*)&Cf[(size_t)r * N + c] = o;
                    if (OM == 1 || OM == 2)
                        *(__half2*)&Ch[(size_t)r * N + c] = __floats2half2_rn(o.x, o.y);
                }
            }
        }
    }
}

// ---------------- pad embeddings ----------------
__global__ void pad_emb_h(const float* __restrict__ in, __half* __restrict__ out) {
    int i = blockIdx.x * 256 + threadIdx.x;
    if (i >= BS * KPAD) return;
    int r = i / KPAD, c = i - r * KPAD;
    out[i] = (c < F_IN) ? __float2half(in[(size_t)r * F_IN + c]) : __half(0.f);
}

// ---------------- batched transpose+pad+quantize ----------------
#define NTR 13
struct TrDesc { const float* in; __half* out; int K; int N; int KP; int tileStart; };
struct TrPack { TrDesc d[NTR]; };

__global__ void transpose_batch(TrPack p) {
    __shared__ float t[32][33];
    const int bt = blockIdx.x;
    int mi = 0;
#pragma unroll
    for (int i = 1; i < NTR; i++)
        if (bt >= p.d[i].tileStart) mi = i;
    const TrDesc de = p.d[mi];
    const int lt = bt - de.tileStart;
    const int ktiles = de.KP >> 5;
    const int k0 = (lt % ktiles) * 32;
    const int n0 = (lt / ktiles) * 32;
    const int x = threadIdx.x, y = threadIdx.y;
#pragma unroll
    for (int j = 0; j < 32; j += 8) {
        int kk = k0 + y + j;
        t[y + j][x] = (kk < de.K && n0 + x < de.N)
                      ? de.in[(size_t)kk * de.N + n0 + x] : 0.f;
    }
    __syncthreads();
#pragma unroll
    for (int j = 0; j < 32; j += 8)
        if (n0 + y + j < de.N)
            de.out[(size_t)(n0 + y + j) * de.KP + k0 + x] = __float2half(t[x][y + j]);
}

// ---------------- concat q/k/v biases ----------------
__global__ void concat_bias(const float* __restrict__ bq, const float* __restrict__ bk,
                            const float* __restrict__ bv, float* __restrict__ out) {
    int i = blockIdx.x * 256 + threadIdx.x;
    if (i >= NLAY * QKVN) return;
    int l = i / QKVN, c = i - l * QKVN;
    float v;
    if (c < DM)           v = bq[l * DM + c];
    else if (c < 2 * DM)  v = bk[l * DM + c - DM];
    else                  v = bv[l * DM + c - 2 * DM];
    out[i] = v;
}

// ---------------- kv = sum_s k^T v ----------------
__global__ __launch_bounds__(256) void kv_kernel(
    const __half* __restrict__ k, const __half* __restrict__ v,
    float* __restrict__ kvpart, float* __restrict__ kspart)
{
    const int bh = blockIdx.x;
    const int b = bh >> 3, h = bh & 7;
    const int chunk = blockIdx.y;
    const int s0 = chunk * KV_CH;
    __shared__ float ksm[64][65];
    __shared__ float vsm[64][64];
    const int tid = threadIdx.x;
    const int m = tid & 63;
    const int dgrp = tid >> 6;
    float acc[16];
#pragma unroll
    for (int i = 0; i < 16; i++) acc[i] = 0.f;
    float kacc = 0.f;

    for (int c = 0; c < KV_CH; c += 64) {
#pragma unroll
        for (int i = 0; i < 8; i++) {
            int idx = tid + i * 256;
            int r = idx >> 5, cc = idx & 31;
            size_t base = (size_t)(b * SEQ + s0 + c + r) * DM + h * HD;
            float2 kf = __half22float2(((const __half2*)(k + base))[cc]);
            float2 vf = __half22float2(((const __half2*)(v + base))[cc]);
            ksm[r][2 * cc] = kf.x; ksm[r][2 * cc + 1] = kf.y;
            vsm[r][2 * cc] = vf.x; vsm[r][2 * cc + 1] = vf.y;
        }
        __syncthreads();
        for (int s = 0; s < 64; s++) {
            float vv = vsm[s][m];
#pragma unroll
            for (int i = 0; i < 16; i++)
                acc[i] = fmaf(ksm[s][dgrp * 16 + i], vv, acc[i]);
        }
        if (tid < 64) {
            float tt = 0.f;
            for (int s = 0; s < 64; s++) tt += ksm[s][tid];
            kacc += tt;
        }
        __syncthreads();
    }
#pragma unroll
    for (int i = 0; i < 16; i++) {
        int d = dgrp * 16 + i;
        kvpart[((size_t)(chunk * BH + bh) * HD + d) * HD + m] = acc[i];
    }
    if (tid < 64) kspart[(size_t)(chunk * BH + bh) * HD + tid] = kacc;
}

// ---------------- fused partial reduce (kv + ks) ----------------
__global__ void reduce_all(const float* __restrict__ pkv, const float* __restrict__ pks,
                           float* __restrict__ kv, float* __restrict__ ks) {
    int i = blockIdx.x * 256 + threadIdx.x;   // BH*HD*HD = 262144
    float a = 0.f;
#pragma unroll
    for (int c = 0; c < NCHUNK; c++) a += pkv[(size_t)c * (BH * HD * HD) + i];
    kv[i] = a;
    if (i < BH * HD) {
        float s = 0.f;
#pragma unroll
        for (int c = 0; c < NCHUNK; c++) s += pks[(size_t)c * (BH * HD) + i];
        ks[i] = s;
    }
}

// ---------------- attention apply ----------------
__global__ __launch_bounds__(256) void attn_kernel(
    const __half* __restrict__ q, const float* __restrict__ kv,
    const float* __restrict__ ks, __half* __restrict__ out)
{
    const int bh = blockIdx.x;
    const int b = bh >> 3, h = bh & 7;
    const int s0 = blockIdx.y * 64;
    __shared__ float kvsm[64][65];
    __shared__ float qsm[64][65];
    __shared__ float zsm[64];
    __shared__ float kssm[64];
    const int tid = threadIdx.x;
#pragma unroll
    for (int i = 0; i < 8; i++) {
        int idx = tid + i * 256;
        int r = idx >> 5, cc = idx & 31;
        float2 qf = __half22float2(
            ((const __half2*)(q + (size_t)(b * SEQ + s0 + r) * DM + h * HD))[cc]);
        qsm[r][2 * cc] = qf.x; qsm[r][2 * cc + 1] = qf.y;
    }
#pragma unroll
    for (int i = 0; i < 16; i++) {
        int idx = tid + i * 256;
        int d = idx >> 6, m = idx & 63;
        kvsm[d][m] = kv[((size_t)bh * HD + d) * HD + m];
    }
    if (tid < 64) kssm[tid] = ks[bh * HD + tid];
    __syncthreads();
    if (tid < 64) {
        float a = 0.f;
        for (int d = 0; d < 64; d++) a = fmaf(qsm[tid][d], kssm[d], a);
        zsm[tid] = 1.f / (a + EPS_ATTN);
    }
    __syncthreads();
    const int m = tid & 63;
    const int tgrp = tid >> 6;
#pragma unroll
    for (int i = 0; i < 16; i++) {
        int tt = tgrp * 16 + i;
        float a = 0.f;
#pragma unroll
        for (int d = 0; d < 64; d++) a = fmaf(qsm[tt][d], kvsm[d][m], a);
        out[(size_t)(b * SEQ + s0 + tt) * DM + h * HD + m] = __float2half(a * zsm[tt]);
    }
}

// ---------------- block reduce helper ----------------
__device__ __forceinline__ float bsum128(float v, float* sm) {
#pragma unroll
    for (int o = 16; o > 0; o >>= 1) v += __shfl_down_sync(0xffffffffu, v, o);
    int w = threadIdx.x >> 5;
    if ((threadIdx.x & 31) == 0) sm[w] = v;
    __syncthreads();
    float r = sm[0] + sm[1] + sm[2] + sm[3];
    __syncthreads();
    return r;
}

// ---------------- layernorm: f32 out + fp16 copy ----------------
__global__ __launch_bounds__(128) void ln_kernel(
    const float* __restrict__ in, const float* __restrict__ g,
    const float* __restrict__ b, float* __restrict__ out,
    __half* __restrict__ hout)
{
    __shared__ float sm[4];
    const int row = blockIdx.x;
    const int tid = threadIdx.x;
    float4 v = ((const float4*)(in + (size_t)row * DM))[tid];
    float s  = v.x + v.y + v.z + v.w;
    float sq = v.x * v.x + v.y * v.y + v.z * v.z + v.w * v.w;
    s  = bsum128(s, sm);
    sq = bsum128(sq, sm);
    float mu = s * (1.f / DM);
    float var = sq * (1.f / DM) - mu * mu;
    float rstd = rsqrtf(var + EPS_LN);
    float4 gg = ((const float4*)g)[tid];
    float4 bb = ((const float4*)b)[tid];
    float4 o;
    o.x = (v.x - mu) * rstd * gg.x + bb.x;
    o.y = (v.y - mu) * rstd * gg.y + bb.y;
    o.z = (v.z - mu) * rstd * gg.z + bb.z;
    o.w = (v.w - mu) * rstd * gg.w + bb.w;
    ((float4*)(out + (size_t)row * DM))[tid] = o;
    ((__half2*)(hout + (size_t)row * DM))[tid * 2 + 0] = __floats2half2_rn(o.x, o.y);
    ((__half2*)(hout + (size_t)row * DM))[tid * 2 + 1] = __floats2half2_rn(o.z, o.w);
}

// ---------------- fused final LN + out proj ----------------
__global__ __launch_bounds__(128) void final_kernel(
    const float* __restrict__ in, const float* __restrict__ g,
    const float* __restrict__ b, const float* __restrict__ w,
    const float* __restrict__ bout, float* __restrict__ out)
{
    __shared__ float sm[4];
    const int row = blockIdx.x;
    const int tid = threadIdx.x;
    float4 v = ((const float4*)(in + (size_t)row * DM))[tid];
    float s  = v.x + v.y + v.z + v.w;
    float sq = v.x * v.x + v.y * v.y + v.z * v.z + v.w * v.w;
    s  = bsum128(s, sm);
    sq = bsum128(sq, sm);
    float mu = s * (1.f / DM);
    float var = sq * (1.f / DM) - mu * mu;
    float rstd = rsqrtf(var + EPS_LN);
    float4 gg = ((const float4*)g)[tid];
    float4 bb = ((const float4*)b)[tid];
    float4 ww = ((const float4*)w)[tid];
    float acc = ((v.x - mu) * rstd * gg.x + bb.x) * ww.x
              + ((v.y - mu) * rstd * gg.y + bb.y) * ww.y
              + ((v.z - mu) * rstd * gg.z + bb.z) * ww.z
              + ((v.w - mu) * rstd * gg.w + bb.w) * ww.w;
    acc = bsum128(acc, sm);
    if (tid == 0) out[row] = acc + bout[0];
}

extern "C" void kernel_launch(void* const* d_in, const int* in_sizes, int n_in,
                              void* d_out, int out_size)
{
    const float* emb   = (const float*)d_in[0];
    const float* W0    = (const float*)d_in[1];
    const float* b0    = (const float*)d_in[2];
    const float* Wq    = (const float*)d_in[3];
    const float* bq    = (const float*)d_in[4];
    const float* Wk    = (const float*)d_in[5];
    const float* bk    = (const float*)d_in[6];
    const float* Wv    = (const float*)d_in[7];
    const float* bv    = (const float*)d_in[8];
    const float* Wo    = (const float*)d_in[9];
    const float* bo    = (const float*)d_in[10];
    const float* ln1s  = (const float*)d_in[11];
    const float* ln1b  = (const float*)d_in[12];
    const float* W1    = (const float*)d_in[13];
    const float* b1    = (const float*)d_in[14];
    const float* W2    = (const float*)d_in[15];
    const float* b2    = (const float*)d_in[16];
    const float* ln2s  = (const float*)d_in[17];
    const float* ln2b  = (const float*)d_in[18];
    const float* lnfs  = (const float*)d_in[19];
    const float* lnfb  = (const float*)d_in[20];
    const float* Wout  = (const float*)d_in[21];
    const float* bout  = (const float*)d_in[22];
    float* out = (float*)d_out;

    // template instantiations used
    auto gemm_in   = gemm_t<10, DM,   0, false, 2>;
    auto gemm_qkv  = gemm_t<8,  QKVN, 3, false, 3>;
    auto gemm_wo   = gemm_t<8,  DM,   0, true,  0>;
    auto gemm_ffn1 = gemm_t<8,  FF,   2, false, 1>;
    auto gemm_ffn2 = gemm_t<16, DM,   0, true,  0>;
    cudaFuncSetAttribute(gemm_in,   cudaFuncAttributeMaxDynamicSharedMemorySize, GEMM_SMEM);
    cudaFuncSetAttribute(gemm_qkv,  cudaFuncAttributeMaxDynamicSharedMemorySize, GEMM_SMEM);
    cudaFuncSetAttribute(gemm_wo,   cudaFuncAttributeMaxDynamicSharedMemorySize, GEMM_SMEM);
    cudaFuncSetAttribute(gemm_ffn1, cudaFuncAttributeMaxDynamicSharedMemorySize, GEMM_SMEM);
    cudaFuncSetAttribute(gemm_ffn2, cudaFuncAttributeMaxDynamicSharedMemorySize, GEMM_SMEM);

    __half *he, *hx, *hq, *hk, *hv, *ht, *hh;
    __half *w0t, *wqkvt, *wot, *w1t, *w2t;
    float *px, *py, *pkvp, *pksp, *pkv, *pks, *bqkv;
    cudaGetSymbolAddress((void**)&he,  g_he);
    cudaGetSymbolAddress((void**)&hx,  g_hx);
    cudaGetSymbolAddress((void**)&hq,  g_hq);
    cudaGetSymbolAddress((void**)&hk,  g_hk);
    cudaGetSymbolAddress((void**)&hv,  g_hv);
    cudaGetSymbolAddress((void**)&ht,  g_ht);
    cudaGetSymbolAddress((void**)&hh,  g_hh);
    cudaGetSymbolAddress((void**)&px,  g_x);
    cudaGetSymbolAddress((void**)&py,  g_y);
    cudaGetSymbolAddress((void**)&pkvp, g_kvpart);
    cudaGetSymbolAddress((void**)&pksp, g_kspart);
    cudaGetSymbolAddress((void**)&pkv, g_kv);
    cudaGetSymbolAddress((void**)&pks, g_ks);
    cudaGetSymbolAddress((void**)&w0t, g_w0t);
    cudaGetSymbolAddress((void**)&wqkvt, g_wqkvt);
    cudaGetSymbolAddress((void**)&wot, g_wot);
    cudaGetSymbolAddress((void**)&w1t, g_w1t);
    cudaGetSymbolAddress((void**)&w2t, g_w2t);
    cudaGetSymbolAddress((void**)&bqkv, g_bqkv);

    // ---- prep ----
    pad_emb_h<<<(BS * KPAD + 255) / 256, 256>>>(emb, he);
    concat_bias<<<(NLAY * QKVN + 255) / 256, 256>>>(bq, bk, bv, bqkv);

    TrPack pack;
    int tileOff = 0;
    auto addTr = [&](int idx, const float* in, __half* outp, int K, int N, int KP) {
        pack.d[idx].in = in; pack.d[idx].out = outp;
        pack.d[idx].K = K; pack.d[idx].N = N; pack.d[idx].KP = KP;
        pack.d[idx].tileStart = tileOff;
        tileOff += (KP / 32) * ((N + 31) / 32);
    };
    int di = 0;
    addTr(di++, W0, w0t, F_IN, DM, KPAD);
    for (int l = 0; l < NLAY; l++) {
        __half* wl = wqkvt + (size_t)l * QKVN * DM;
        addTr(di++, Wq + (size_t)l * DM * DM, wl,                        DM, DM, DM);
        addTr(di++, Wk + (size_t)l * DM * DM, wl + (size_t)DM * DM,      DM, DM, DM);
        addTr(di++, Wv + (size_t)l * DM * DM, wl + (size_t)2 * DM * DM,  DM, DM, DM);
        addTr(di++, Wo + (size_t)l * DM * DM, wot + (size_t)l * DM * DM, DM, DM, DM);
        addTr(di++, W1 + (size_t)l * DM * FF, w1t + (size_t)l * DM * FF, DM, FF, DM);
        addTr(di++, W2 + (size_t)l * FF * DM, w2t + (size_t)l * FF * DM, FF, DM, FF);
    }
    transpose_batch<<<tileOff, dim3(32, 8)>>>(pack);

    // ---- input projection ----
    gemm_in<<<dim3(DM / GBN, BS / GBM), 256, GEMM_SMEM>>>(
        he, w0t, b0, nullptr, px, hx, nullptr, nullptr);

    for (int l = 0; l < NLAY; l++) {
        const __half* wqkv_l = wqkvt + (size_t)l * QKVN * DM;
        const __half* wot_l  = wot + (size_t)l * DM * DM;
        const __half* w1t_l  = w1t + (size_t)l * DM * FF;
        const __half* w2t_l  = w2t + (size_t)l * FF * DM;
        const float* bqkv_l = bqkv + (size_t)l * QKVN;
        const float* bo_l = bo + (size_t)l * DM;
        const float* b1_l = b1 + (size_t)l * FF;
        const float* b2_l = b2 + (size_t)l * DM;

        gemm_qkv<<<dim3(QKVN / GBN, BS / GBM), 256, GEMM_SMEM>>>(
            hx, wqkv_l, bqkv_l, nullptr, nullptr, hq, hk, hv);

        kv_kernel<<<dim3(BH, NCHUNK), 256>>>(hk, hv, pkvp, pksp);
        reduce_all<<<(BH * HD * HD) / 256, 256>>>(pkvp, pksp, pkv, pks);
        attn_kernel<<<dim3(BH, SEQ / 64), 256>>>(hq, pkv, pks, ht);

        gemm_wo<<<dim3(DM / GBN, BS / GBM), 256, GEMM_SMEM>>>(
            ht, wot_l, bo_l, px, py, nullptr, nullptr, nullptr);
        ln_kernel<<<BS, 128>>>(py, ln1s + (size_t)l * DM, ln1b + (size_t)l * DM, px, hx);

        gemm_ffn1<<<dim3(FF / GBN, BS / GBM), 256, GEMM_SMEM>>>(
            hx, w1t_l, b1_l, nullptr, nullptr, hh, nullptr, nullptr);
        gemm_ffn2<<<dim3(DM / GBN, BS / GBM), 256, GEMM_SMEM>>>(
            hh, w2t_l, b2_l, px, py, nullptr, nullptr, nullptr);
        ln_kernel<<<BS, 128>>>(py, ln2s + (size_t)l * DM, ln2b + (size_t)l * DM, px, hx);
    }

    final_kernel<<<BS, 128>>>(px, lnfs, lnfb, Wout, bout, out);
}

// round 10
// speedup vs baseline: 1.3468x; 1.1974x over previous
#include <cuda_runtime.h>
#include <cuda_fp16.h>
#include <math.h>
#include <stdint.h>

// ---------------- problem constants ----------------
#define BATCH 8
#define SEQ   4096
#define F_IN  586
#define KPAD  640
#define DM    512
#define NH    8
#define HD    64
#define FF    1024
#define NLAY  2
#define BS    (BATCH*SEQ)
#define BH    (BATCH*NH)
#define QKVN  (3*DM)
#define EPS_ATTN 1e-6f
#define EPS_LN   1e-5f
#define NCHUNK 8
#define KV_CH  (SEQ/NCHUNK)    // 512
#define KVXR   80              // kvx rows: 64 kvT + 1 ks + 15 pad

// ---------------- scratch ----------------
__device__ __half g_he[BS*KPAD];
__device__ __half g_hx[BS*DM];
__device__ __half g_hq[BS*DM];
__device__ __half g_hk[BS*DM];
__device__ __half g_hv[BS*DM];
__device__ __half g_ht[BS*DM];
__device__ __half g_hh[BS*FF];
__device__ __half g_kT[(size_t)BH*HD*SEQ];
__device__ __half g_vT[(size_t)BH*HD*SEQ];
__device__ float  g_x [BS*DM];
__device__ float  g_y [BS*DM];
__device__ float  g_kvpart[NCHUNK*BH*HD*HD];
__device__ float  g_ks[BH*HD];
__device__ __half g_kvx[BH*KVXR*HD];
__device__ __half g_w0t [DM*KPAD];
__device__ __half g_wqkvt[NLAY*QKVN*DM];
__device__ __half g_wot [NLAY*DM*DM];
__device__ __half g_w1t [NLAY*FF*DM];
__device__ __half g_w2t [NLAY*DM*FF];
__device__ float  g_bqkv[NLAY*QKVN];

// ---------------- helpers ----------------
__device__ __forceinline__ uint32_t smem_u32(const void* p) {
    uint32_t a;
    asm("{ .reg .u64 t; cvta.to.shared.u64 t, %1; cvt.u32.u64 %0, t; }" : "=r"(a) : "l"(p));
    return a;
}
__device__ __forceinline__ void cp_async16(uint32_t dst, const void* src) {
    asm volatile("cp.async.cg.shared.global [%0], [%1], 16;"
                 :: "r"(dst), "l"(src) : "memory");
}
#define CP_COMMIT() asm volatile("cp.async.commit_group;" ::: "memory")
#define CP_WAIT0()  asm volatile("cp.async.wait_group 0;" ::: "memory")

__device__ __forceinline__ void ldmatrix_x4(uint32_t* r, uint32_t addr) {
    asm volatile("ldmatrix.sync.aligned.m8n8.x4.shared.b16 {%0,%1,%2,%3}, [%4];"
                 : "=r"(r[0]), "=r"(r[1]), "=r"(r[2]), "=r"(r[3]) : "r"(addr));
}
__device__ __forceinline__ void mma_f16(float* c, const uint32_t* a, uint32_t b0, uint32_t b1) {
    asm volatile(
        "mma.sync.aligned.m16n8k16.row.col.f32.f16.f16.f32 "
        "{%0,%1,%2,%3}, {%4,%5,%6,%7}, {%8,%9}, {%0,%1,%2,%3};"
        : "+f"(c[0]), "+f"(c[1]), "+f"(c[2]), "+f"(c[3])
        : "r"(a[0]), "r"(a[1]), "r"(a[2]), "r"(a[3]), "r"(b0), "r"(b1));
}

// ---------------- templated fp16 tensor-core GEMM ----------------
#define GBM 128
#define GBN 128
#define TILE_B 16384
#define GEMM_SMEM (4*TILE_B)

template<int KITERS, int N, int ACT, bool HAS_RES, int OM>
__global__ __launch_bounds__(256) void gemm_t(
    const __half* __restrict__ A, const __half* __restrict__ BT,
    const float* __restrict__ bias, const float* __restrict__ res,
    float* __restrict__ Cf, __half* __restrict__ Ch,
    __half* __restrict__ Ch2, __half* __restrict__ Ch3)
{
    constexpr int K = KITERS * 64;
    extern __shared__ char smraw[];
    const uint32_t smBase = smem_u32(smraw);
    const int tid  = threadIdx.x;
    const int warp = tid >> 5;
    const int lane = tid & 31;
    const int g = lane >> 2;
    const int t = lane & 3;
    const int warpM = warp & 3;
    const int warpN = warp >> 2;
    const int rowBase = blockIdx.y * GBM;
    const int colBase = blockIdx.x * GBN;

    const int ldr = tid >> 3;
    const int ldc = tid & 7;
    auto loadTile = [&](int it, int buf) {
        const int k0 = it * 64;
#pragma unroll
        for (int p = 0; p < 4; p++) {
            int row = p * 32 + ldr;
            uint32_t dst = smBase + buf * TILE_B + row * 128 + ((ldc ^ (row & 7)) << 4);
            cp_async16(dst, &A[(size_t)(rowBase + row) * K + k0 + ldc * 8]);
        }
#pragma unroll
        for (int p = 0; p < 4; p++) {
            int row = p * 32 + ldr;
            uint32_t dst = smBase + 2 * TILE_B + buf * TILE_B + row * 128 + ((ldc ^ (row & 7)) << 4);
            cp_async16(dst, &BT[(size_t)(colBase + row) * K + k0 + ldc * 8]);
        }
    };

    float acc[2][8][4];
#pragma unroll
    for (int mt = 0; mt < 2; mt++)
#pragma unroll
        for (int nt = 0; nt < 8; nt++)
#pragma unroll
            for (int i = 0; i < 4; i++) acc[mt][nt][i] = 0.f;

    loadTile(0, 0);
    CP_COMMIT();

    const int lrow = lane & 15;
    const int khalf = lane >> 4;

#pragma unroll 1
    for (int it = 0; it < KITERS; ++it) {
        const int buf = it & 1;
        CP_WAIT0();
        __syncthreads();
        if (it + 1 < KITERS) {
            loadTile(it + 1, buf ^ 1);
            CP_COMMIT();
        }
        const uint32_t Abase = smBase + buf * TILE_B;
        const uint32_t Bbase = smBase + 2 * TILE_B + buf * TILE_B;
#pragma unroll
        for (int ks = 0; ks < 4; ks++) {
            const int cIdx = 2 * ks + khalf;
            uint32_t a[2][4];
#pragma unroll
            for (int mt = 0; mt < 2; mt++) {
                int row = warpM * 32 + mt * 16 + lrow;
                ldmatrix_x4(a[mt], Abase + row * 128 + ((cIdx ^ (row & 7)) << 4));
            }
            uint32_t br[4][4];
#pragma unroll
            for (int j = 0; j < 4; j++) {
                int row = warpN * 64 + j * 16 + lrow;
                ldmatrix_x4(br[j], Bbase + row * 128 + ((cIdx ^ (row & 7)) << 4));
            }
#pragma unroll
            for (int mt = 0; mt < 2; mt++)
#pragma unroll
                for (int j = 0; j < 4; j++) {
                    mma_f16(acc[mt][2 * j],     a[mt], br[j][0], br[j][2]);
                    mma_f16(acc[mt][2 * j + 1], a[mt], br[j][1], br[j][3]);
                }
        }
    }

#pragma unroll
    for (int mt = 0; mt < 2; mt++) {
#pragma unroll
        for (int sub = 0; sub < 2; sub++) {
            const int r = rowBase + warpM * 32 + mt * 16 + g + sub * 8;
#pragma unroll
            for (int nt = 0; nt < 8; nt++) {
                const int c = colBase + warpN * 64 + nt * 8 + 2 * t;
                float2 o;
                o.x = acc[mt][nt][sub * 2 + 0];
                o.y = acc[mt][nt][sub * 2 + 1];
                float2 bi = *(const float2*)&bias[c];
                o.x += bi.x; o.y += bi.y;
                if (HAS_RES) {
                    float2 rr = *(const float2*)&res[(size_t)r * N + c];
                    o.x += rr.x; o.y += rr.y;
                }
                if (ACT == 1 || (ACT == 3 && c < 2 * DM)) {
                    o.x = (o.x > 0.f) ? (o.x + 1.f) : expf(o.x);
                    o.y = (o.y > 0.f) ? (o.y + 1.f) : expf(o.y);
                } else if (ACT == 2) {
                    o.x = fmaxf(o.x, 0.f);
                    o.y = fmaxf(o.y, 0.f);
                }
                if (OM == 3) {
                    int reg = c >> 9;
                    int col = c & (DM - 1);
                    __half* hd = (reg == 0) ? Ch : (reg == 1) ? Ch2 : Ch3;
                    *(__half2*)&hd[(size_t)r * DM + col] = __floats2half2_rn(o.x, o.y);
                } else {
                    if (OM == 0 || OM == 2)
                        *(float2*)&Cf[(size_t)r * N + c] = o;
                    if (OM == 1 || OM == 2)
                        *(__half2*)&Ch[(size_t)r * N + c] = __floats2half2_rn(o.x, o.y);
                }
            }
        }
    }
}

// ---------------- pad embeddings ----------------
__global__ void pad_emb_h(const float* __restrict__ in, __half* __restrict__ out) {
    int i = blockIdx.x * 256 + threadIdx.x;
    if (i >= BS * KPAD) return;
    int r = i / KPAD, c = i - r * KPAD;
    out[i] = (c < F_IN) ? __float2half(in[(size_t)r * F_IN + c]) : __half(0.f);
}

// ---------------- batched weight transpose ----------------
#define NTR 13
struct TrDesc { const float* in; __half* out; int K; int N; int KP; int tileStart; };
struct TrPack { TrDesc d[NTR]; };

__global__ void transpose_batch(TrPack p) {
    __shared__ float t[32][33];
    const int bt = blockIdx.x;
    int mi = 0;
#pragma unroll
    for (int i = 1; i < NTR; i++)
        if (bt >= p.d[i].tileStart) mi = i;
    const TrDesc de = p.d[mi];
    const int lt = bt - de.tileStart;
    const int ktiles = de.KP >> 5;
    const int k0 = (lt % ktiles) * 32;
    const int n0 = (lt / ktiles) * 32;
    const int x = threadIdx.x, y = threadIdx.y;
#pragma unroll
    for (int j = 0; j < 32; j += 8) {
        int kk = k0 + y + j;
        t[y + j][x] = (kk < de.K && n0 + x < de.N)
                      ? de.in[(size_t)kk * de.N + n0 + x] : 0.f;
    }
    __syncthreads();
#pragma unroll
    for (int j = 0; j < 32; j += 8)
        if (n0 + y + j < de.N)
            de.out[(size_t)(n0 + y + j) * de.KP + k0 + x] = __float2half(t[x][y + j]);
}

// ---------------- concat q/k/v biases ----------------
__global__ void concat_bias(const float* __restrict__ bq, const float* __restrict__ bk,
                            const float* __restrict__ bv, float* __restrict__ out) {
    int i = blockIdx.x * 256 + threadIdx.x;
    if (i >= NLAY * QKVN) return;
    int l = i / QKVN, c = i - l * QKVN;
    float v;
    if (c < DM)           v = bq[l * DM + c];
    else if (c < 2 * DM)  v = bk[l * DM + c - DM];
    else                  v = bv[l * DM + c - 2 * DM];
    out[i] = v;
}

// ---------------- transpose k,v per head: [BS,DM] -> [BH,HD,SEQ] ----------------
__global__ __launch_bounds__(128) void trans_kv(
    const __half* __restrict__ k, const __half* __restrict__ v,
    __half* __restrict__ kT, __half* __restrict__ vT)
{
    __shared__ __half tk[64][66];
    __shared__ __half tv[64][66];
    const int bh = blockIdx.x;
    const int s0 = blockIdx.y * 64;
    const int b = bh >> 3, h = bh & 7;
    const int tid = threadIdx.x;
#pragma unroll
    for (int p = 0; p < 16; p++) {
        int idx = tid + p * 128;
        int row = idx >> 5, c2 = idx & 31;
        size_t base = (size_t)(b * SEQ + s0 + row) * DM + h * HD;
        __half2 kk = ((const __half2*)(k + base))[c2];
        __half2 vv = ((const __half2*)(v + base))[c2];
        tk[row][2 * c2] = __low2half(kk);  tk[row][2 * c2 + 1] = __high2half(kk);
        tv[row][2 * c2] = __low2half(vv);  tv[row][2 * c2 + 1] = __high2half(vv);
    }
    __syncthreads();
    const int w = tid >> 5, lane = tid & 31;
#pragma unroll
    for (int it = 0; it < 16; it++) {
        int d = it * 4 + w;
        __half2 ko = __halves2half2(tk[2 * lane][d], tk[2 * lane + 1][d]);
        __half2 vo = __halves2half2(tv[2 * lane][d], tv[2 * lane + 1][d]);
        size_t o = ((size_t)bh * HD + d) * SEQ + s0 + 2 * lane;
        *(__half2*)&kT[o] = ko;
        *(__half2*)&vT[o] = vo;
    }
}

// ---------------- ks[bh][d] = sum_s kT[bh][d][s] ----------------
__global__ __launch_bounds__(256) void ks_kernel(
    const __half* __restrict__ kT, float* __restrict__ ks)
{
    const int bh = blockIdx.x;
    const int w = threadIdx.x >> 5, lane = threadIdx.x & 31;
#pragma unroll 1
    for (int it = 0; it < 8; it++) {
        int d = it * 8 + w;
        const __half2* row = (const __half2*)(kT + ((size_t)bh * HD + d) * SEQ);
        float s = 0.f;
#pragma unroll 4
        for (int kk = 0; kk < 64; kk++) {
            float2 f = __half22float2(row[lane + kk * 32]);
            s += f.x + f.y;
        }
#pragma unroll
        for (int o = 16; o > 0; o >>= 1) s += __shfl_down_sync(0xffffffffu, s, o);
        if (lane == 0) ks[bh * HD + d] = s;
    }
}

// ---------------- kv partial via mma: kvT_part[m,d] = sum_s vT[m,s] kT[d,s] ----------------
__global__ __launch_bounds__(128) void kv_mma(
    const __half* __restrict__ kT, const __half* __restrict__ vT,
    float* __restrict__ kvpart)
{
    __shared__ __half smA[2][64 * 64];   // vT tile
    __shared__ __half smB[2][64 * 64];   // kT tile
    const uint32_t aBase0 = smem_u32(smA);
    const uint32_t bBase0 = smem_u32(smB);
    const int bh = blockIdx.x;
    const int chunk = blockIdx.y;
    const int tid = threadIdx.x;
    const int warp = tid >> 5;
    const int lane = tid & 31;
    const int g = lane >> 2, t = lane & 3;
    const int lrow = lane & 15, khalf = lane >> 4;
    const int s0 = chunk * KV_CH;

    const int ldr = tid >> 3;      // 0..15
    const int ldc = tid & 7;
    auto loadTile = [&](int it, int buf) {
        const int k0 = s0 + it * 64;
#pragma unroll
        for (int p = 0; p < 4; p++) {
            int row = p * 16 + ldr;
            uint32_t off = buf * 8192 + row * 128 + ((ldc ^ (row & 7)) << 4);
            size_t src = ((size_t)bh * HD + row) * SEQ + k0 + ldc * 8;
            cp_async16(aBase0 + off, &vT[src]);
            cp_async16(bBase0 + off, &kT[src]);
        }
    };

    float acc[4][2][4];
#pragma unroll
    for (int mt = 0; mt < 4; mt++)
#pragma unroll
        for (int j = 0; j < 2; j++)
#pragma unroll
            for (int i = 0; i < 4; i++) acc[mt][j][i] = 0.f;

    loadTile(0, 0);
    CP_COMMIT();

#pragma unroll 1
    for (int it = 0; it < KV_CH / 64; ++it) {
        const int buf = it & 1;
        CP_WAIT0();
        __syncthreads();
        if (it + 1 < KV_CH / 64) {
            loadTile(it + 1, buf ^ 1);
            CP_COMMIT();
        }
        const uint32_t Ab = aBase0 + buf * 8192;
        const uint32_t Bb = bBase0 + buf * 8192;
#pragma unroll
        for (int ks = 0; ks < 4; ks++) {
            const int cIdx = 2 * ks + khalf;
            uint32_t a[4][4];
#pragma unroll
            for (int mt = 0; mt < 4; mt++) {
                int row = mt * 16 + lrow;
                ldmatrix_x4(a[mt], Ab + row * 128 + ((cIdx ^ (row & 7)) << 4));
            }
            uint32_t br[4];
            {
                int row = warp * 16 + lrow;
                ldmatrix_x4(br, Bb + row * 128 + ((cIdx ^ (row & 7)) << 4));
            }
#pragma unroll
            for (int mt = 0; mt < 4; mt++) {
                mma_f16(acc[mt][0], a[mt], br[0], br[2]);
                mma_f16(acc[mt][1], a[mt], br[1], br[3]);
            }
        }
    }

    // write partials [m][d] f32
#pragma unroll
    for (int mt = 0; mt < 4; mt++)
#pragma unroll
        for (int j = 0; j < 2; j++)
#pragma unroll
            for (int sub = 0; sub < 2; sub++) {
                int m = mt * 16 + g + sub * 8;
                int d = warp * 16 + j * 8 + 2 * t;
                float2 o;
                o.x = acc[mt][j][sub * 2 + 0];
                o.y = acc[mt][j][sub * 2 + 1];
                *(float2*)&kvpart[(((size_t)chunk * BH + bh) * HD + m) * HD + d] = o;
            }
}

// ---------------- reduce partials + build kvx [BH][80][64] fp16 ----------------
__global__ __launch_bounds__(256) void reduce_kvx(
    const float* __restrict__ kvpart, const float* __restrict__ ks,
    __half* __restrict__ kvx)
{
    const int bh = blockIdx.x;
    for (int idx = threadIdx.x; idx < KVXR * HD; idx += 256) {
        int n = idx >> 6, d = idx & 63;
        float v = 0.f;
        if (n < 64) {
#pragma unroll
            for (int c = 0; c < NCHUNK; c++)
                v += kvpart[(((size_t)c * BH + bh) * HD + n) * HD + d];
        } else if (n == 64) {
            v = ks[bh * HD + d];
        }
        kvx[((size_t)bh * KVXR + n) * HD + d] = __float2half(v);
    }
}

// ---------------- attention via mma: C[64,80] = q_tile @ kvx^T; z from col 64 ----------------
__global__ __launch_bounds__(128) void attn_mma(
    const __half* __restrict__ q, const __half* __restrict__ kvx,
    __half* __restrict__ out)
{
    __shared__ __half smA[64 * 64];     // q tile
    __shared__ __half smB[KVXR * 64];   // kvx tile
    const uint32_t aBase = smem_u32(smA);
    const uint32_t bBase = smem_u32(smB);
    const int bh = blockIdx.x;
    const int s0 = blockIdx.y * 64;
    const int b = bh >> 3, h = bh & 7;
    const int tid = threadIdx.x;
    const int warp = tid >> 5;
    const int lane = tid & 31;
    const int g = lane >> 2, t = lane & 3;
    const int lrow = lane & 15, khalf = lane >> 4;

    {
        const int ldr = tid >> 3, ldc = tid & 7;
#pragma unroll
        for (int p = 0; p < 4; p++) {          // q: 64 rows
            int row = p * 16 + ldr;
            uint32_t dst = aBase + row * 128 + ((ldc ^ (row & 7)) << 4);
            cp_async16(dst, &q[(size_t)(b * SEQ + s0 + row) * DM + h * HD + ldc * 8]);
        }
#pragma unroll
        for (int p = 0; p < 5; p++) {          // kvx: 80 rows
            int row = p * 16 + ldr;
            uint32_t dst = bBase + row * 128 + ((ldc ^ (row & 7)) << 4);
            cp_async16(dst, &kvx[((size_t)bh * KVXR + row) * HD + ldc * 8]);
        }
        CP_COMMIT();
        CP_WAIT0();
        __syncthreads();
    }

    float acc[10][4];
#pragma unroll
    for (int nt = 0; nt < 10; nt++)
#pragma unroll
        for (int i = 0; i < 4; i++) acc[nt][i] = 0.f;

#pragma unroll
    for (int ks = 0; ks < 4; ks++) {
        const int cIdx = 2 * ks + khalf;
        uint32_t a[4];
        {
            int row = warp * 16 + lrow;
            ldmatrix_x4(a, aBase + row * 128 + ((cIdx ^ (row & 7)) << 4));
        }
#pragma unroll
        for (int j = 0; j < 5; j++) {
            uint32_t br[4];
            int row = j * 16 + lrow;
            ldmatrix_x4(br, bBase + row * 128 + ((cIdx ^ (row & 7)) << 4));
            mma_f16(acc[2 * j],     a, br[0], br[2]);
            mma_f16(acc[2 * j + 1], a, br[1], br[3]);
        }
    }

    // z from column 64 (n-tile 8, t==0 slot), broadcast within row group
    float d0 = __shfl_sync(0xffffffffu, acc[8][0], lane & 28);
    float d1 = __shfl_sync(0xffffffffu, acc[8][2], lane & 28);
    float z0 = 1.f / (d0 + EPS_ATTN);
    float z1 = 1.f / (d1 + EPS_ATTN);

    const int r0 = s0 + warp * 16 + g;
#pragma unroll
    for (int nt = 0; nt < 8; nt++) {
        int c = nt * 8 + 2 * t;
        *(__half2*)&out[(size_t)(b * SEQ + r0) * DM + h * HD + c] =
            __floats2half2_rn(acc[nt][0] * z0, acc[nt][1] * z0);
        *(__half2*)&out[(size_t)(b * SEQ + r0 + 8) * DM + h * HD + c] =
            __floats2half2_rn(acc[nt][2] * z1, acc[nt][3] * z1);
    }
}

// ---------------- block reduce helper ----------------
__device__ __forceinline__ float bsum128(float v, float* sm) {
#pragma unroll
    for (int o = 16; o > 0; o >>= 1) v += __shfl_down_sync(0xffffffffu, v, o);
    int w = threadIdx.x >> 5;
    if ((threadIdx.x & 31) == 0) sm[w] = v;
    __syncthreads();
    float r = sm[0] + sm[1] + sm[2] + sm[3];
    __syncthreads();
    return r;
}

// ---------------- layernorm: f32 out + fp16 copy ----------------
__global__ __launch_bounds__(128) void ln_kernel(
    const float* __restrict__ in, const float* __restrict__ g,
    const float* __restrict__ b, float* __restrict__ out,
    __half* __restrict__ hout)
{
    __shared__ float sm[4];
    const int row = blockIdx.x;
    const int tid = threadIdx.x;
    float4 v = ((const float4*)(in + (size_t)row * DM))[tid];
    float s  = v.x + v.y + v.z + v.w;
    float sq = v.x * v.x + v.y * v.y + v.z * v.z + v.w * v.w;
    s  = bsum128(s, sm);
    sq = bsum128(sq, sm);
    float mu = s * (1.f / DM);
    float var = sq * (1.f / DM) - mu * mu;
    float rstd = rsqrtf(var + EPS_LN);
    float4 gg = ((const float4*)g)[tid];
    float4 bb = ((const float4*)b)[tid];
    float4 o;
    o.x = (v.x - mu) * rstd * gg.x + bb.x;
    o.y = (v.y - mu) * rstd * gg.y + bb.y;
    o.z = (v.z - mu) * rstd * gg.z + bb.z;
    o.w = (v.w - mu) * rstd * gg.w + bb.w;
    ((float4*)(out + (size_t)row * DM))[tid] = o;
    ((__half2*)(hout + (size_t)row * DM))[tid * 2 + 0] = __floats2half2_rn(o.x, o.y);
    ((__half2*)(hout + (size_t)row * DM))[tid * 2 + 1] = __floats2half2_rn(o.z, o.w);
}

// ---------------- fused final LN + out proj ----------------
__global__ __launch_bounds__(128) void final_kernel(
    const float* __restrict__ in, const float* __restrict__ g,
    const float* __restrict__ b, const float* __restrict__ w,
    const float* __restrict__ bout, float* __restrict__ out)
{
    __shared__ float sm[4];
    const int row = blockIdx.x;
    const int tid = threadIdx.x;
    float4 v = ((const float4*)(in + (size_t)row * DM))[tid];
    float s  = v.x + v.y + v.z + v.w;
    float sq = v.x * v.x + v.y * v.y + v.z * v.z + v.w * v.w;
    s  = bsum128(s, sm);
    sq = bsum128(sq, sm);
    float mu = s * (1.f / DM);
    float var = sq * (1.f / DM) - mu * mu;
    float rstd = rsqrtf(var + EPS_LN);
    float4 gg = ((const float4*)g)[tid];
    float4 bb = ((const float4*)b)[tid];
    float4 ww = ((const float4*)w)[tid];
    float acc = ((v.x - mu) * rstd * gg.x + bb.x) * ww.x
              + ((v.y - mu) * rstd * gg.y + bb.y) * ww.y
              + ((v.z - mu) * rstd * gg.z + bb.z) * ww.z
              + ((v.w - mu) * rstd * gg.w + bb.w) * ww.w;
    acc = bsum128(acc, sm);
    if (tid == 0) out[row] = acc + bout[0];
}

extern "C" void kernel_launch(void* const* d_in, const int* in_sizes, int n_in,
                              void* d_out, int out_size)
{
    const float* emb   = (const float*)d_in[0];
    const float* W0    = (const float*)d_in[1];
    const float* b0    = (const float*)d_in[2];
    const float* Wq    = (const float*)d_in[3];
    const float* bq    = (const float*)d_in[4];
    const float* Wk    = (const float*)d_in[5];
    const float* bk    = (const float*)d_in[6];
    const float* Wv    = (const float*)d_in[7];
    const float* bv    = (const float*)d_in[8];
    const float* Wo    = (const float*)d_in[9];
    const float* bo    = (const float*)d_in[10];
    const float* ln1s  = (const float*)d_in[11];
    const float* ln1b  = (const float*)d_in[12];
    const float* W1    = (const float*)d_in[13];
    const float* b1    = (const float*)d_in[14];
    const float* W2    = (const float*)d_in[15];
    const float* b2    = (const float*)d_in[16];
    const float* ln2s  = (const float*)d_in[17];
    const float* ln2b  = (const float*)d_in[18];
    const float* lnfs  = (const float*)d_in[19];
    const float* lnfb  = (const float*)d_in[20];
    const float* Wout  = (const float*)d_in[21];
    const float* bout  = (const float*)d_in[22];
    float* out = (float*)d_out;

    auto gemm_in   = gemm_t<10, DM,   0, false, 2>;
    auto gemm_qkv  = gemm_t<8,  QKVN, 3, false, 3>;
    auto gemm_wo   = gemm_t<8,  DM,   0, true,  0>;
    auto gemm_ffn1 = gemm_t<8,  FF,   2, false, 1>;
    auto gemm_ffn2 = gemm_t<16, DM,   0, true,  0>;
    cudaFuncSetAttribute(gemm_in,   cudaFuncAttributeMaxDynamicSharedMemorySize, GEMM_SMEM);
    cudaFuncSetAttribute(gemm_qkv,  cudaFuncAttributeMaxDynamicSharedMemorySize, GEMM_SMEM);
    cudaFuncSetAttribute(gemm_wo,   cudaFuncAttributeMaxDynamicSharedMemorySize, GEMM_SMEM);
    cudaFuncSetAttribute(gemm_ffn1, cudaFuncAttributeMaxDynamicSharedMemorySize, GEMM_SMEM);
    cudaFuncSetAttribute(gemm_ffn2, cudaFuncAttributeMaxDynamicSharedMemorySize, GEMM_SMEM);

    __half *he, *hx, *hq, *hk, *hv, *ht, *hh, *kT, *vT, *kvx;
    __half *w0t, *wqkvt, *wot, *w1t, *w2t;
    float *px, *py, *pkvp, *pks, *bqkv;
    cudaGetSymbolAddress((void**)&he,  g_he);
    cudaGetSymbolAddress((void**)&hx,  g_hx);
    cudaGetSymbolAddress((void**)&hq,  g_hq);
    cudaGetSymbolAddress((void**)&hk,  g_hk);
    cudaGetSymbolAddress((void**)&hv,  g_hv);
    cudaGetSymbolAddress((void**)&ht,  g_ht);
    cudaGetSymbolAddress((void**)&hh,  g_hh);
    cudaGetSymbolAddress((void**)&kT,  g_kT);
    cudaGetSymbolAddress((void**)&vT,  g_vT);
    cudaGetSymbolAddress((void**)&kvx, g_kvx);
    cudaGetSymbolAddress((void**)&px,  g_x);
    cudaGetSymbolAddress((void**)&py,  g_y);
    cudaGetSymbolAddress((void**)&pkvp, g_kvpart);
    cudaGetSymbolAddress((void**)&pks, g_ks);
    cudaGetSymbolAddress((void**)&w0t, g_w0t);
    cudaGetSymbolAddress((void**)&wqkvt, g_wqkvt);
    cudaGetSymbolAddress((void**)&wot, g_wot);
    cudaGetSymbolAddress((void**)&w1t, g_w1t);
    cudaGetSymbolAddress((void**)&w2t, g_w2t);
    cudaGetSymbolAddress((void**)&bqkv, g_bqkv);

    // ---- prep ----
    pad_emb_h<<<(BS * KPAD + 255) / 256, 256>>>(emb, he);
    concat_bias<<<(NLAY * QKVN + 255) / 256, 256>>>(bq, bk, bv, bqkv);

    TrPack pack;
    int tileOff = 0;
    auto addTr = [&](int idx, const float* in, __half* outp, int K, int N, int KP) {
        pack.d[idx].in = in; pack.d[idx].out = outp;
        pack.d[idx].K = K; pack.d[idx].N = N; pack.d[idx].KP = KP;
        pack.d[idx].tileStart = tileOff;
        tileOff += (KP / 32) * ((N + 31) / 32);
    };
    int di = 0;
    addTr(di++, W0, w0t, F_IN, DM, KPAD);
    for (int l = 0; l < NLAY; l++) {
        __half* wl = wqkvt + (size_t)l * QKVN * DM;
        addTr(di++, Wq + (size_t)l * DM * DM, wl,                        DM, DM, DM);
        addTr(di++, Wk + (size_t)l * DM * DM, wl + (size_t)DM * DM,      DM, DM, DM);
        addTr(di++, Wv + (size_t)l * DM * DM, wl + (size_t)2 * DM * DM,  DM, DM, DM);
        addTr(di++, Wo + (size_t)l * DM * DM, wot + (size_t)l * DM * DM, DM, DM, DM);
        addTr(di++, W1 + (size_t)l * DM * FF, w1t + (size_t)l * DM * FF, DM, FF, DM);
        addTr(di++, W2 + (size_t)l * FF * DM, w2t + (size_t)l * FF * DM, FF, DM, FF);
    }
    transpose_batch<<<tileOff, dim3(32, 8)>>>(pack);

    // ---- input projection ----
    gemm_in<<<dim3(DM / GBN, BS / GBM), 256, GEMM_SMEM>>>(
        he, w0t, b0, nullptr, px, hx, nullptr, nullptr);

    for (int l = 0; l < NLAY; l++) {
        const __half* wqkv_l = wqkvt + (size_t)l * QKVN * DM;
        const __half* wot_l  = wot + (size_t)l * DM * DM;
        const __half* w1t_l  = w1t + (size_t)l * DM * FF;
        const __half* w2t_l  = w2t + (size_t)l * FF * DM;
        const float* bqkv_l = bqkv + (size_t)l * QKVN;
        const float* bo_l = bo + (size_t)l * DM;
        const float* b1_l = b1 + (size_t)l * FF;
        const float* b2_l = b2 + (size_t)l * DM;

        gemm_qkv<<<dim3(QKVN / GBN, BS / GBM), 256, GEMM_SMEM>>>(
            hx, wqkv_l, bqkv_l, nullptr, nullptr, hq, hk, hv);

        trans_kv<<<dim3(BH, SEQ / 64), 128>>>(hk, hv, kT, vT);
        ks_kernel<<<BH, 256>>>(kT, pks);
        kv_mma<<<dim3(BH, NCHUNK), 128>>>(kT, vT, pkvp);
        reduce_kvx<<<BH, 256>>>(pkvp, pks, kvx);
        attn_mma<<<dim3(BH, SEQ / 64), 128>>>(hq, kvx, ht);

        gemm_wo<<<dim3(DM / GBN, BS / GBM), 256, GEMM_SMEM>>>(
            ht, wot_l, bo_l, px, py, nullptr, nullptr, nullptr);
        ln_kernel<<<BS, 128>>>(py, ln1s + (size_t)l * DM, ln1b + (size_t)l * DM, px, hx);

        gemm_ffn1<<<dim3(FF / GBN, BS / GBM), 256, GEMM_SMEM>>>(
            hx, w1t_l, b1_l, nullptr, nullptr, hh, nullptr, nullptr);
        gemm_ffn2<<<dim3(DM / GBN, BS / GBM), 256, GEMM_SMEM>>>(
            hh, w2t_l, b2_l, px, py, nullptr, nullptr, nullptr);
        ln_kernel<<<BS, 128>>>(py, ln2s + (size_t)l * DM, ln2b + (size_t)l * DM, px, hx);
    }

    final_kernel<<<BS, 128>>>(px, lnfs, lnfb, Wout, bout, out);
}

// round 13
// speedup vs baseline: 1.4395x; 1.0688x over previous
#include <cuda_runtime.h>
#include <cuda_fp16.h>
#include <math.h>
#include <stdint.h>

// ---------------- problem constants ----------------
#define BATCH 8
#define SEQ   4096
#define F_IN  586
#define KPAD  640
#define DM    512
#define NH    8
#define HD    64
#define FF    1024
#define NLAY  2
#define BS    (BATCH*SEQ)
#define BH    (BATCH*NH)
#define QKVN  (3*DM)
#define EPS_ATTN 1e-6f
#define EPS_LN   1e-5f
#define NCHUNK 8
#define KV_CH  (SEQ/NCHUNK)    // 512
#define KVXR   80              // kv rows: 64 kvT + 1 ks + 15 pad
#define TSTR   136             // staging stride in halves (128 + 8 pad)

// ---------------- scratch ----------------
__device__ __half g_he[BS*KPAD];
__device__ __half g_hx[BS*DM];
__device__ __half g_hq[BS*DM];
__device__ __half g_ht[BS*DM];
__device__ __half g_hh[BS*FF];
__device__ __half g_kT[(size_t)BH*HD*SEQ];        // [bh][64][SEQ]
__device__ __half g_vT[(size_t)BH*KVXR*SEQ];      // [bh][80][SEQ]; rows 64..79 fixed
__device__ float  g_x [BS*DM];
__device__ float  g_y [BS*DM];
__device__ float  g_kvpart[NCHUNK*BH*KVXR*HD];
__device__ __half g_kvx[BH*KVXR*HD];
__device__ __half g_w0t [DM*KPAD];
__device__ __half g_wqkvt[NLAY*QKVN*DM];
__device__ __half g_wot [NLAY*DM*DM];
__device__ __half g_w1t [NLAY*FF*DM];
__device__ __half g_w2t [NLAY*DM*FF];
__device__ float  g_bqkv[NLAY*QKVN];

// ---------------- helpers ----------------
__device__ __forceinline__ uint32_t smem_u32(const void* p) {
    uint32_t a;
    asm("{ .reg .u64 t; cvta.to.shared.u64 t, %1; cvt.u32.u64 %0, t; }" : "=r"(a) : "l"(p));
    return a;
}
__device__ __forceinline__ void cp_async16(uint32_t dst, const void* src) {
    asm volatile("cp.async.cg.shared.global [%0], [%1], 16;"
                 :: "r"(dst), "l"(src) : "memory");
}
#define CP_COMMIT() asm volatile("cp.async.commit_group;" ::: "memory")
#define CP_WAIT0()  asm volatile("cp.async.wait_group 0;" ::: "memory")

__device__ __forceinline__ void ldmatrix_x4(uint32_t* r, uint32_t addr) {
    asm volatile("ldmatrix.sync.aligned.m8n8.x4.shared.b16 {%0,%1,%2,%3}, [%4];"
                 : "=r"(r[0]), "=r"(r[1]), "=r"(r[2]), "=r"(r[3]) : "r"(addr));
}
__device__ __forceinline__ void mma_f16(float* c, const uint32_t* a, uint32_t b0, uint32_t b1) {
    asm volatile(
        "mma.sync.aligned.m16n8k16.row.col.f32.f16.f16.f32 "
        "{%0,%1,%2,%3}, {%4,%5,%6,%7}, {%8,%9}, {%0,%1,%2,%3};"
        : "+f"(c[0]), "+f"(c[1]), "+f"(c[2]), "+f"(c[3])
        : "r"(a[0]), "r"(a[1]), "r"(a[2]), "r"(a[3]), "r"(b0), "r"(b1));
}

// ---------------- templated fp16 tensor-core GEMM ----------------
// OM: 0 = f32 only, 1 = fp16 only, 2 = f32 + fp16,
//     3 = qkv: q -> Ch [M,512]; k,v -> head-transposed Ch2 (kT), Ch3 (vT)
#define GBM 128
#define GBN 128
#define TILE_B 16384
#define GEMM_SMEM (4*TILE_B)

template<int KITERS, int N, int ACT, bool HAS_RES, int OM>
__global__ __launch_bounds__(256) void gemm_t(
    const __half* __restrict__ A, const __half* __restrict__ BT,
    const float* __restrict__ bias, const float* __restrict__ res,
    float* __restrict__ Cf, __half* __restrict__ Ch,
    __half* __restrict__ Ch2, __half* __restrict__ Ch3)
{
    constexpr int K = KITERS * 64;
    extern __shared__ char smraw[];
    const uint32_t smBase = smem_u32(smraw);
    const int tid  = threadIdx.x;
    const int warp = tid >> 5;
    const int lane = tid & 31;
    const int g = lane >> 2;
    const int t = lane & 3;
    const int warpM = warp & 3;
    const int warpN = warp >> 2;
    const int rowBase = blockIdx.y * GBM;
    const int colBase = blockIdx.x * GBN;

    const int ldr = tid >> 3;
    const int ldc = tid & 7;
    auto loadTile = [&](int it, int buf) {
        const int k0 = it * 64;
#pragma unroll
        for (int p = 0; p < 4; p++) {
            int row = p * 32 + ldr;
            uint32_t dst = smBase + buf * TILE_B + row * 128 + ((ldc ^ (row & 7)) << 4);
            cp_async16(dst, &A[(size_t)(rowBase + row) * K + k0 + ldc * 8]);
        }
#pragma unroll
        for (int p = 0; p < 4; p++) {
            int row = p * 32 + ldr;
            uint32_t dst = smBase + 2 * TILE_B + buf * TILE_B + row * 128 + ((ldc ^ (row & 7)) << 4);
            cp_async16(dst, &BT[(size_t)(colBase + row) * K + k0 + ldc * 8]);
        }
    };

    float acc[2][8][4];
#pragma unroll
    for (int mt = 0; mt < 2; mt++)
#pragma unroll
        for (int nt = 0; nt < 8; nt++)
#pragma unroll
            for (int i = 0; i < 4; i++) acc[mt][nt][i] = 0.f;

    loadTile(0, 0);
    CP_COMMIT();

    const int lrow = lane & 15;
    const int khalf = lane >> 4;

#pragma unroll 1
    for (int it = 0; it < KITERS; ++it) {
        const int buf = it & 1;
        CP_WAIT0();
        __syncthreads();
        if (it + 1 < KITERS) {
            loadTile(it + 1, buf ^ 1);
            CP_COMMIT();
        }
        const uint32_t Abase = smBase + buf * TILE_B;
        const uint32_t Bbase = smBase + 2 * TILE_B + buf * TILE_B;
#pragma unroll
        for (int ks = 0; ks < 4; ks++) {
            const int cIdx = 2 * ks + khalf;
            uint32_t a[2][4];
#pragma unroll
            for (int mt = 0; mt < 2; mt++) {
                int row = warpM * 32 + mt * 16 + lrow;
                ldmatrix_x4(a[mt], Abase + row * 128 + ((cIdx ^ (row & 7)) << 4));
            }
            uint32_t br[4][4];
#pragma unroll
            for (int j = 0; j < 4; j++) {
                int row = warpN * 64 + j * 16 + lrow;
                ldmatrix_x4(br[j], Bbase + row * 128 + ((cIdx ^ (row & 7)) << 4));
            }
#pragma unroll
            for (int mt = 0; mt < 2; mt++)
#pragma unroll
                for (int j = 0; j < 4; j++) {
                    mma_f16(acc[mt][2 * j],     a[mt], br[j][0], br[j][2]);
                    mma_f16(acc[mt][2 * j + 1], a[mt], br[j][1], br[j][3]);
                }
        }
    }

    // ---- epilogue ----
    const bool stage = (OM == 3) && (colBase >= 512);   // k or v segment
    __half* sh = (__half*)smraw;                        // 128 cols x TSTR tokens
    if (stage) __syncthreads();                         // all ldmatrix reads done

#pragma unroll
    for (int mt = 0; mt < 2; mt++) {
#pragma unroll
        for (int sub = 0; sub < 2; sub++) {
            const int rl = warpM * 32 + mt * 16 + g + sub * 8;
            const int r = rowBase + rl;
#pragma unroll
            for (int nt = 0; nt < 8; nt++) {
                const int cl = warpN * 64 + nt * 8 + 2 * t;
                const int c = colBase + cl;
                float2 o;
                o.x = acc[mt][nt][sub * 2 + 0];
                o.y = acc[mt][nt][sub * 2 + 1];
                float2 bi = *(const float2*)&bias[c];
                o.x += bi.x; o.y += bi.y;
                if (HAS_RES) {
                    float2 rr = *(const float2*)&res[(size_t)r * N + c];
                    o.x += rr.x; o.y += rr.y;
                }
                if (ACT == 1 || (ACT == 3 && c < 2 * DM)) {
                    o.x = (o.x > 0.f) ? (o.x + 1.f) : expf(o.x);
                    o.y = (o.y > 0.f) ? (o.y + 1.f) : expf(o.y);
                } else if (ACT == 2) {
                    o.x = fmaxf(o.x, 0.f);
                    o.y = fmaxf(o.y, 0.f);
                }
                if (OM == 3) {
                    if (!stage) {
                        // q segment: global column c < 512
                        *(__half2*)&Ch[(size_t)r * DM + c] = __floats2half2_rn(o.x, o.y);
                    } else {
                        sh[cl * TSTR + rl]       = __float2half(o.x);
                        sh[(cl + 1) * TSTR + rl] = __float2half(o.y);
                    }
                } else {
                    if (OM == 0 || OM == 2)
                        *(float2*)&Cf[(size_t)r * N + c] = o;
                    if (OM == 1 || OM == 2)
                        *(__half2*)&Ch[(size_t)r * N + c] = __floats2half2_rn(o.x, o.y);
                }
            }
        }
    }

    if (stage) {
        __syncthreads();
        const int seg = colBase >> 9;          // 1 = k, 2 = v
        const int rowd = tid >> 1;             // c_local 0..127
        const int hs = tid & 1;                // s half (64 tokens each)
        const int hloc = rowd >> 6, d = rowd & 63;
        const int b = rowBase >> 12;
        const int s0 = rowBase & (SEQ - 1);
        const int hbase = (colBase & 511) >> 6;
        const int bh = b * NH + hbase + hloc;
        __half* dstT = (seg == 1) ? Ch2 : Ch3;
        const size_t rstr = (seg == 1) ? HD : KVXR;
        const uint4* s4 = (const uint4*)(sh + rowd * TSTR + hs * 64);
        uint4* d4 = (uint4*)(dstT + ((size_t)bh * rstr + d) * SEQ + s0 + hs * 64);
#pragma unroll
        for (int i = 0; i < 8; i++) d4[i] = s4[i];
    }
}

// ---------------- pad embeddings ----------------
__global__ void pad_emb_h(const float* __restrict__ in, __half* __restrict__ out) {
    int i = blockIdx.x * 256 + threadIdx.x;
    if (i >= BS * KPAD) return;
    int r = i / KPAD, c = i - r * KPAD;
    out[i] = (c < F_IN) ? __float2half(in[(size_t)r * F_IN + c]) : __half(0.f);
}

// ---------------- init vT tail rows (64 = ones, 65..79 = zeros) ----------------
__global__ void init_vtail(__half* __restrict__ vT) {
    int i = blockIdx.x * 256 + threadIdx.x;      // BH*16*SEQ
    if (i >= BH * 16 * SEQ) return;
    int bh = i / (16 * SEQ);
    int rem = i - bh * 16 * SEQ;
    int row = 64 + rem / SEQ;
    int s = rem % SEQ;
    vT[((size_t)bh * KVXR + row) * SEQ + s] = (row == 64) ? __half(1.f) : __half(0.f);
}

// ---------------- batched weight transpose ----------------
#define NTR 13
struct TrDesc { const float* in; __half* out; int K; int N; int KP; int tileStart; };
struct TrPack { TrDesc d[NTR]; };

__global__ void transpose_batch(TrPack p) {
    __shared__ float t[32][33];
    const int bt = blockIdx.x;
    int mi = 0;
#pragma unroll
    for (int i = 1; i < NTR; i++)
        if (bt >= p.d[i].tileStart) mi = i;
    const TrDesc de = p.d[mi];
    const int lt = bt - de.tileStart;
    const int ktiles = de.KP >> 5;
    const int k0 = (lt % ktiles) * 32;
    const int n0 = (lt / ktiles) * 32;
    const int x = threadIdx.x, y = threadIdx.y;
#pragma unroll
    for (int j = 0; j < 32; j += 8) {
        int kk = k0 + y + j;
        t[y + j][x] = (kk < de.K && n0 + x < de.N)
                      ? de.in[(size_t)kk * de.N + n0 + x] : 0.f;
    }
    __syncthreads();
#pragma unroll
    for (int j = 0; j < 32; j += 8)
        if (n0 + y + j < de.N)
            de.out[(size_t)(n0 + y + j) * de.KP + k0 + x] = __float2half(t[x][y + j]);
}

// ---------------- concat q/k/v biases ----------------
__global__ void concat_bias(const float* __restrict__ bq, const float* __restrict__ bk,
                            const float* __restrict__ bv, float* __restrict__ out) {
    int i = blockIdx.x * 256 + threadIdx.x;
    if (i >= NLAY * QKVN) return;
    int l = i / QKVN, c = i - l * QKVN;
    float v;
    if (c < DM)           v = bq[l * DM + c];
    else if (c < 2 * DM)  v = bk[l * DM + c - DM];
    else                  v = bv[l * DM + c - 2 * DM];
    out[i] = v;
}

// ---------------- kv partials via mma: part[m,d] = sum_s vT80[m,s] kT[d,s] ----------------
__global__ __launch_bounds__(128) void kv_mma(
    const __half* __restrict__ kT, const __half* __restrict__ vT,
    float* __restrict__ kvpart)
{
    __shared__ __half smA[2][KVXR * 64];   // vT tile (80 rows)
    __shared__ __half smB[2][64 * 64];     // kT tile
    const uint32_t aBase0 = smem_u32(smA);
    const uint32_t bBase0 = smem_u32(smB);
    const int bh = blockIdx.x;
    const int chunk = blockIdx.y;
    const int tid = threadIdx.x;
    const int warp = tid >> 5;
    const int lane = tid & 31;
    const int g = lane >> 2, t = lane & 3;
    const int lrow = lane & 15, khalf = lane >> 4;
    const int s0 = chunk * KV_CH;

    const int ldr = tid >> 3;      // 0..15
    const int ldc = tid & 7;
    auto loadTile = [&](int it, int buf) {
        const int k0 = s0 + it * 64;
#pragma unroll
        for (int p = 0; p < 5; p++) {
            int row = p * 16 + ldr;
            uint32_t off = buf * (KVXR * 128) + row * 128 + ((ldc ^ (row & 7)) << 4);
            cp_async16(aBase0 + off, &vT[((size_t)bh * KVXR + row) * SEQ + k0 + ldc * 8]);
        }
#pragma unroll
        for (int p = 0; p < 4; p++) {
            int row = p * 16 + ldr;
            uint32_t off = buf * 8192 + row * 128 + ((ldc ^ (row & 7)) << 4);
            cp_async16(bBase0 + off, &kT[((size_t)bh * HD + row) * SEQ + k0 + ldc * 8]);
        }
    };

    float acc[5][2][4];
#pragma unroll
    for (int mt = 0; mt < 5; mt++)
#pragma unroll
        for (int j = 0; j < 2; j++)
#pragma unroll
            for (int i = 0; i < 4; i++) acc[mt][j][i] = 0.f;

    loadTile(0, 0);
    CP_COMMIT();

#pragma unroll 1
    for (int it = 0; it < KV_CH / 64; ++it) {
        const int buf = it & 1;
        CP_WAIT0();
        __syncthreads();
        if (it + 1 < KV_CH / 64) {
            loadTile(it + 1, buf ^ 1);
            CP_COMMIT();
        }
        const uint32_t Ab = aBase0 + buf * (KVXR * 128);
        const uint32_t Bb = bBase0 + buf * 8192;
#pragma unroll
        for (int ks = 0; ks < 4; ks++) {
            const int cIdx = 2 * ks + khalf;
            uint32_t a[5][4];
#pragma unroll
            for (int mt = 0; mt < 5; mt++) {
                int row = mt * 16 + lrow;
                ldmatrix_x4(a[mt], Ab + row * 128 + ((cIdx ^ (row & 7)) << 4));
            }
            uint32_t br[4];
            {
                int row = warp * 16 + lrow;
                ldmatrix_x4(br, Bb + row * 128 + ((cIdx ^ (row & 7)) << 4));
            }
#pragma unroll
            for (int mt = 0; mt < 5; mt++) {
                mma_f16(acc[mt][0], a[mt], br[0], br[2]);
                mma_f16(acc[mt][1], a[mt], br[1], br[3]);
            }
        }
    }

#pragma unroll
    for (int mt = 0; mt < 5; mt++)
#pragma unroll
        for (int j = 0; j < 2; j++)
#pragma unroll
            for (int sub = 0; sub < 2; sub++) {
                int m = mt * 16 + g + sub * 8;
                int d = warp * 16 + j * 8 + 2 * t;
                float2 o;
                o.x = acc[mt][j][sub * 2 + 0];
                o.y = acc[mt][j][sub * 2 + 1];
                *(float2*)&kvpart[(((size_t)chunk * BH + bh) * KVXR + m) * HD + d] = o;
            }
}

// ---------------- reduce partials -> kvx [BH][80][64] fp16 ----------------
__global__ __launch_bounds__(256) void reduce_kvx(
    const float* __restrict__ kvpart, __half* __restrict__ kvx)
{
    const int bh = blockIdx.x;
    for (int idx = threadIdx.x; idx < KVXR * HD; idx += 256) {
        float v = 0.f;
#pragma unroll
        for (int c = 0; c < NCHUNK; c++)
            v += kvpart[((size_t)c * BH + bh) * (KVXR * HD) + idx];
        kvx[(size_t)bh * (KVXR * HD) + idx] = __float2half(v);
    }
}

// ---------------- attention via mma: C[64,80] = q_tile @ kvx^T; z from col 64 ----------------
__global__ __launch_bounds__(128) void attn_mma(
    const __half* __restrict__ q, const __half* __restrict__ kvx,
    __half* __restrict__ out)
{
    __shared__ __half smA[64 * 64];
    __shared__ __half smB[KVXR * 64];
    const uint32_t aBase = smem_u32(smA);
    const uint32_t bBase = smem_u32(smB);
    const int bh = blockIdx.x;
    const int s0 = blockIdx.y * 64;
    const int b = bh >> 3, h = bh & 7;
    const int tid = threadIdx.x;
    const int warp = tid >> 5;
    const int lane = tid & 31;
    const int g = lane >> 2, t = lane & 3;
    const int lrow = lane & 15, khalf = lane >> 4;

    {
        const int ldr = tid >> 3, ldc = tid & 7;
#pragma unroll
        for (int p = 0; p < 4; p++) {
            int row = p * 16 + ldr;
            uint32_t dst = aBase + row * 128 + ((ldc ^ (row & 7)) << 4);
            cp_async16(dst, &q[(size_t)(b * SEQ + s0 + row) * DM + h * HD + ldc * 8]);
        }
#pragma unroll
        for (int p = 0; p < 5; p++) {
            int row = p * 16 + ldr;
            uint32_t dst = bBase + row * 128 + ((ldc ^ (row & 7)) << 4);
            cp_async16(dst, &kvx[((size_t)bh * KVXR + row) * HD + ldc * 8]);
        }
        CP_COMMIT();
        CP_WAIT0();
        __syncthreads();
    }

    float acc[10][4];
#pragma unroll
    for (int nt = 0; nt < 10; nt++)
#pragma unroll
        for (int i = 0; i < 4; i++) acc[nt][i] = 0.f;

#pragma unroll
    for (int ks = 0; ks < 4; ks++) {
        const int cIdx = 2 * ks + khalf;
        uint32_t a[4];
        {
            int row = warp * 16 + lrow;
            ldmatrix_x4(a, aBase + row * 128 + ((cIdx ^ (row & 7)) << 4));
        }
#pragma unroll
        for (int j = 0; j < 5; j++) {
            uint32_t br[4];
            int row = j * 16 + lrow;
            ldmatrix_x4(br, bBase + row * 128 + ((cIdx ^ (row & 7)) << 4));
            mma_f16(acc[2 * j],     a, br[0], br[2]);
            mma_f16(acc[2 * j + 1], a, br[1], br[3]);
        }
    }

    float d0 = __shfl_sync(0xffffffffu, acc[8][0], lane & 28);
    float d1 = __shfl_sync(0xffffffffu, acc[8][2], lane & 28);
    float z0 = 1.f / (d0 + EPS_ATTN);
    float z1 = 1.f / (d1 + EPS_ATTN);

    const int r0 = s0 + warp * 16 + g;
#pragma unroll
    for (int nt = 0; nt < 8; nt++) {
        int c = nt * 8 + 2 * t;
        *(__half2*)&out[(size_t)(b * SEQ + r0) * DM + h * HD + c] =
            __floats2half2_rn(acc[nt][0] * z0, acc[nt][1] * z0);
        *(__half2*)&out[(size_t)(b * SEQ + r0 + 8) * DM + h * HD + c] =
            __floats2half2_rn(acc[nt][2] * z1, acc[nt][3] * z1);
    }
}

// ---------------- block reduce helper ----------------
__device__ __forceinline__ float bsum128(float v, float* sm) {
#pragma unroll
    for (int o = 16; o > 0; o >>= 1) v += __shfl_down_sync(0xffffffffu, v, o);
    int w = threadIdx.x >> 5;
    if ((threadIdx.x & 31) == 0) sm[w] = v;
    __syncthreads();
    float r = sm[0] + sm[1] + sm[2] + sm[3];
    __syncthreads();
    return r;
}

// ---------------- layernorm: f32 out + fp16 copy ----------------
__global__ __launch_bounds__(128) void ln_kernel(
    const float* __restrict__ in, const float* __restrict__ g,
    const float* __restrict__ b, float* __restrict__ out,
    __half* __restrict__ hout)
{
    __shared__ float sm[4];
    const int row = blockIdx.x;
    const int tid = threadIdx.x;
    float4 v = ((const float4*)(in + (size_t)row * DM))[tid];
    float s  = v.x + v.y + v.z + v.w;
    float sq = v.x * v.x + v.y * v.y + v.z * v.z + v.w * v.w;
    s  = bsum128(s, sm);
    sq = bsum128(sq, sm);
    float mu = s * (1.f / DM);
    float var = sq * (1.f / DM) - mu * mu;
    float rstd = rsqrtf(var + EPS_LN);
    float4 gg = ((const float4*)g)[tid];
    float4 bb = ((const float4*)b)[tid];
    float4 o;
    o.x = (v.x - mu) * rstd * gg.x + bb.x;
    o.y = (v.y - mu) * rstd * gg.y + bb.y;
    o.z = (v.z - mu) * rstd * gg.z + bb.z;
    o.w = (v.w - mu) * rstd * gg.w + bb.w;
    ((float4*)(out + (size_t)row * DM))[tid] = o;
    ((__half2*)(hout + (size_t)row * DM))[tid * 2 + 0] = __floats2half2_rn(o.x, o.y);
    ((__half2*)(hout + (size_t)row * DM))[tid * 2 + 1] = __floats2half2_rn(o.z, o.w);
}

// ---------------- fused final LN + out proj ----------------
__global__ __launch_bounds__(128) void final_kernel(
    const float* __restrict__ in, const float* __restrict__ g,
    const float* __restrict__ b, const float* __restrict__ w,
    const float* __restrict__ bout, float* __restrict__ out)
{
    __shared__ float sm[4];
    const int row = blockIdx.x;
    const int tid = threadIdx.x;
    float4 v = ((const float4*)(in + (size_t)row * DM))[tid];
    float s  = v.x + v.y + v.z + v.w;
    float sq = v.x * v.x + v.y * v.y + v.z * v.z + v.w * v.w;
    s  = bsum128(s, sm);
    sq = bsum128(sq, sm);
    float mu = s * (1.f / DM);
    float var = sq * (1.f / DM) - mu * mu;
    float rstd = rsqrtf(var + EPS_LN);
    float4 gg = ((const float4*)g)[tid];
    float4 bb = ((const float4*)b)[tid];
    float4 ww = ((const float4*)w)[tid];
    float acc = ((v.x - mu) * rstd * gg.x + bb.x) * ww.x
              + ((v.y - mu) * rstd * gg.y + bb.y) * ww.y
              + ((v.z - mu) * rstd * gg.z + bb.z) * ww.z
              + ((v.w - mu) * rstd * gg.w + bb.w) * ww.w;
    acc = bsum128(acc, sm);
    if (tid == 0) out[row] = acc + bout[0];
}

extern "C" void kernel_launch(void* const* d_in, const int* in_sizes, int n_in,
                              void* d_out, int out_size)
{
    const float* emb   = (const float*)d_in[0];
    const float* W0    = (const float*)d_in[1];
    const float* b0    = (const float*)d_in[2];
    const float* Wq    = (const float*)d_in[3];
    const float* bq    = (const float*)d_in[4];
    const float* Wk    = (const float*)d_in[5];
    const float* bk    = (const float*)d_in[6];
    const float* Wv    = (const float*)d_in[7];
    const float* bv    = (const float*)d_in[8];
    const float* Wo    = (const float*)d_in[9];
    const float* bo    = (const float*)d_in[10];
    const float* ln1s  = (const float*)d_in[11];
    const float* ln1b  = (const float*)d_in[12];
    const float* W1    = (const float*)d_in[13];
    const float* b1    = (const float*)d_in[14];
    const float* W2    = (const float*)d_in[15];
    const float* b2    = (const float*)d_in[16];
    const float* ln2s  = (const float*)d_in[17];
    const float* ln2b  = (const float*)d_in[18];
    const float* lnfs  = (const float*)d_in[19];
    const float* lnfb  = (const float*)d_in[20];
    const float* Wout  = (const float*)d_in[21];
    const float* bout  = (const float*)d_in[22];
    float* out = (float*)d_out;

    auto gemm_in   = gemm_t<10, DM,   0, false, 2>;
    auto gemm_qkv  = gemm_t<8,  QKVN, 3, false, 3>;
    auto gemm_wo   = gemm_t<8,  DM,   0, true,  0>;
    auto gemm_ffn1 = gemm_t<8,  FF,   2, false, 1>;
    auto gemm_ffn2 = gemm_t<16, DM,   0, true,  0>;
    cudaFuncSetAttribute(gemm_in,   cudaFuncAttributeMaxDynamicSharedMemorySize, GEMM_SMEM);
    cudaFuncSetAttribute(gemm_qkv,  cudaFuncAttributeMaxDynamicSharedMemorySize, GEMM_SMEM);
    cudaFuncSetAttribute(gemm_wo,   cudaFuncAttributeMaxDynamicSharedMemorySize, GEMM_SMEM);
    cudaFuncSetAttribute(gemm_ffn1, cudaFuncAttributeMaxDynamicSharedMemorySize, GEMM_SMEM);
    cudaFuncSetAttribute(gemm_ffn2, cudaFuncAttributeMaxDynamicSharedMemorySize, GEMM_SMEM);

    __half *he, *hx, *hq, *ht, *hh, *kT, *vT, *kvx;
    __half *w0t, *wqkvt, *wot, *w1t, *w2t;
    float *px, *py, *pkvp, *bqkv;
    cudaGetSymbolAddress((void**)&he,  g_he);
    cudaGetSymbolAddress((void**)&hx,  g_hx);
    cudaGetSymbolAddress((void**)&hq,  g_hq);
    cudaGetSymbolAddress((void**)&ht,  g_ht);
    cudaGetSymbolAddress((void**)&hh,  g_hh);
    cudaGetSymbolAddress((void**)&kT,  g_kT);
    cudaGetSymbolAddress((void**)&vT,  g_vT);
    cudaGetSymbolAddress((void**)&kvx, g_kvx);
    cudaGetSymbolAddress((void**)&px,  g_x);
    cudaGetSymbolAddress((void**)&py,  g_y);
    cudaGetSymbolAddress((void**)&pkvp, g_kvpart);
    cudaGetSymbolAddress((void**)&w0t, g_w0t);
    cudaGetSymbolAddress((void**)&wqkvt, g_wqkvt);
    cudaGetSymbolAddress((void**)&wot, g_wot);
    cudaGetSymbolAddress((void**)&w1t, g_w1t);
    cudaGetSymbolAddress((void**)&w2t, g_w2t);
    cudaGetSymbolAddress((void**)&bqkv, g_bqkv);

    // ---- prep ----
    pad_emb_h<<<(BS * KPAD + 255) / 256, 256>>>(emb, he);
    concat_bias<<<(NLAY * QKVN + 255) / 256, 256>>>(bq, bk, bv, bqkv);
    init_vtail<<<(BH * 16 * SEQ + 255) / 256, 256>>>(vT);

    TrPack pack;
    int tileOff = 0;
    auto addTr = [&](int idx, const float* in, __half* outp, int K, int N, int KP) {
        pack.d[idx].in = in; pack.d[idx].out = outp;
        pack.d[idx].K = K; pack.d[idx].N = N; pack.d[idx].KP = KP;
        pack.d[idx].tileStart = tileOff;
        tileOff += (KP / 32) * ((N + 31) / 32);
    };
    int di = 0;
    addTr(di++, W0, w0t, F_IN, DM, KPAD);
    for (int l = 0; l < NLAY; l++) {
        __half* wl = wqkvt + (size_t)l * QKVN * DM;
        addTr(di++, Wq + (size_t)l * DM * DM, wl,                        DM, DM, DM);
        addTr(di++, Wk + (size_t)l * DM * DM, wl + (size_t)DM * DM,      DM, DM, DM);
        addTr(di++, Wv + (size_t)l * DM * DM, wl + (size_t)2 * DM * DM,  DM, DM, DM);
        addTr(di++, Wo + (size_t)l * DM * DM, wot + (size_t)l * DM * DM, DM, DM, DM);
        addTr(di++, W1 + (size_t)l * DM * FF, w1t + (size_t)l * DM * FF, DM, FF, DM);
        addTr(di++, W2 + (size_t)l * FF * DM, w2t + (size_t)l * FF * DM, FF, DM, FF);
    }
    transpose_batch<<<tileOff, dim3(32, 8)>>>(pack);

    // ---- input projection ----
    gemm_in<<<dim3(DM / GBN, BS / GBM), 256, GEMM_SMEM>>>(
        he, w0t, b0, nullptr, px, hx, nullptr, nullptr);

    for (int l = 0; l < NLAY; l++) {
        const __half* wqkv_l = wqkvt + (size_t)l * QKVN * DM;
        const __half* wot_l  = wot + (size_t)l * DM * DM;
        const __half* w1t_l  = w1t + (size_t)l * DM * FF;
        const __half* w2t_l  = w2t + (size_t)l * FF * DM;
        const float* bqkv_l = bqkv + (size_t)l * QKVN;
        const float* bo_l = bo + (size_t)l * DM;
        const float* b1_l = b1 + (size_t)l * FF;
        const float* b2_l = b2 + (size_t)l * DM;

        // fused q/k/v projection -> hq + head-transposed kT/vT
        gemm_qkv<<<dim3(QKVN / GBN, BS / GBM), 256, GEMM_SMEM>>>(
            hx, wqkv_l, bqkv_l, nullptr, nullptr, hq, kT, vT);

        kv_mma<<<dim3(BH, NCHUNK), 128>>>(kT, vT, pkvp);
        reduce_kvx<<<BH, 256>>>(pkvp, kvx);
        attn_mma<<<dim3(BH, SEQ / 64), 128>>>(hq, kvx, ht);

        gemm_wo<<<dim3(DM / GBN, BS / GBM), 256, GEMM_SMEM>>>(
            ht, wot_l, bo_l, px, py, nullptr, nullptr, nullptr);
        ln_kernel<<<BS, 128>>>(py, ln1s + (size_t)l * DM, ln1b + (size_t)l * DM, px, hx);

        gemm_ffn1<<<dim3(FF / GBN, BS / GBM), 256, GEMM_SMEM>>>(
            hx, w1t_l, b1_l, nullptr, nullptr, hh, nullptr, nullptr);
        gemm_ffn2<<<dim3(DM / GBN, BS / GBM), 256, GEMM_SMEM>>>(
            hh, w2t_l, b2_l, px, py, nullptr, nullptr, nullptr);
        ln_kernel<<<BS, 128>>>(py, ln2s + (size_t)l * DM, ln2b + (size_t)l * DM, px, hx);
    }

    final_kernel<<<BS, 128>>>(px, lnfs, lnfb, Wout, bout, out);
}

// round 14
// speedup vs baseline: 1.5047x; 1.0453x over previous
#include <cuda_runtime.h>
#include <cuda_fp16.h>
#include <math.h>
#include <stdint.h>

// ---------------- problem constants ----------------
#define BATCH 8
#define SEQ   4096
#define F_IN  586
#define KPAD  640
#define DM    512
#define NH    8
#define HD    64
#define FF    1024
#define NLAY  2
#define BS    (BATCH*SEQ)
#define BH    (BATCH*NH)
#define QKVN  (3*DM)
#define EPS_ATTN 1e-6f
#define EPS_LN   1e-5f
#define NCHUNK 8
#define KV_CH  (SEQ/NCHUNK)    // 512
#define KVXR   80              // kv rows: 64 kvT + 1 ks + 15 pad
#define TSTR   136             // staging stride in halves (128 + 8 pad)

// ---------------- scratch ----------------
__device__ __half g_he[BS*KPAD];
__device__ __half g_hx[BS*DM];       // x (LN output / GEMM A / residual)
__device__ __half g_hy[BS*DM];       // pre-LN y
__device__ __half g_hq[BS*DM];
__device__ __half g_ht[BS*DM];
__device__ __half g_hh[BS*FF];
__device__ __half g_kT[(size_t)BH*HD*SEQ];
__device__ __half g_vT[(size_t)BH*KVXR*SEQ];
__device__ float  g_kvpart[NCHUNK*BH*KVXR*HD];
__device__ __half g_kvx[BH*KVXR*HD];
__device__ __half g_w0t [DM*KPAD];
__device__ __half g_wqkvt[NLAY*QKVN*DM];
__device__ __half g_wot [NLAY*DM*DM];
__device__ __half g_w1t [NLAY*FF*DM];
__device__ __half g_w2t [NLAY*DM*FF];
__device__ float  g_bqkv[NLAY*QKVN];

// ---------------- helpers ----------------
__device__ __forceinline__ uint32_t smem_u32(const void* p) {
    uint32_t a;
    asm("{ .reg .u64 t; cvta.to.shared.u64 t, %1; cvt.u32.u64 %0, t; }" : "=r"(a) : "l"(p));
    return a;
}
__device__ __forceinline__ void cp_async16(uint32_t dst, const void* src) {
    asm volatile("cp.async.cg.shared.global [%0], [%1], 16;"
                 :: "r"(dst), "l"(src) : "memory");
}
#define CP_COMMIT() asm volatile("cp.async.commit_group;" ::: "memory")
#define CP_WAIT0()  asm volatile("cp.async.wait_group 0;" ::: "memory")

__device__ __forceinline__ void ldmatrix_x4(uint32_t* r, uint32_t addr) {
    asm volatile("ldmatrix.sync.aligned.m8n8.x4.shared.b16 {%0,%1,%2,%3}, [%4];"
                 : "=r"(r[0]), "=r"(r[1]), "=r"(r[2]), "=r"(r[3]) : "r"(addr));
}
__device__ __forceinline__ void mma_f16(float* c, const uint32_t* a, uint32_t b0, uint32_t b1) {
    asm volatile(
        "mma.sync.aligned.m16n8k16.row.col.f32.f16.f16.f32 "
        "{%0,%1,%2,%3}, {%4,%5,%6,%7}, {%8,%9}, {%0,%1,%2,%3};"
        : "+f"(c[0]), "+f"(c[1]), "+f"(c[2]), "+f"(c[3])
        : "r"(a[0]), "r"(a[1]), "r"(a[2]), "r"(a[3]), "r"(b0), "r"(b1));
}

// ---------------- templated fp16 tensor-core GEMM ----------------
// RES: 0 none, 2 = fp16 residual (resh)
// OM:  1 = fp16 out (Ch), 3 = qkv split (q -> Ch; k,v -> head-transposed Ch2/Ch3)
#define GBM 128
#define GBN 128
#define TILE_B 16384
#define GEMM_SMEM (4*TILE_B)

template<int KITERS, int N, int ACT, int RES, int OM>
__global__ __launch_bounds__(256) void gemm_t(
    const __half* __restrict__ A, const __half* __restrict__ BT,
    const float* __restrict__ bias, const __half* __restrict__ resh,
    __half* __restrict__ Ch, __half* __restrict__ Ch2, __half* __restrict__ Ch3)
{
    constexpr int K = KITERS * 64;
    extern __shared__ char smraw[];
    const uint32_t smBase = smem_u32(smraw);
    const int tid  = threadIdx.x;
    const int warp = tid >> 5;
    const int lane = tid & 31;
    const int g = lane >> 2;
    const int t = lane & 3;
    const int warpM = warp & 3;
    const int warpN = warp >> 2;
    const int rowBase = blockIdx.y * GBM;
    const int colBase = blockIdx.x * GBN;

    const int ldr = tid >> 3;
    const int ldc = tid & 7;
    auto loadTile = [&](int it, int buf) {
        const int k0 = it * 64;
#pragma unroll
        for (int p = 0; p < 4; p++) {
            int row = p * 32 + ldr;
            uint32_t dst = smBase + buf * TILE_B + row * 128 + ((ldc ^ (row & 7)) << 4);
            cp_async16(dst, &A[(size_t)(rowBase + row) * K + k0 + ldc * 8]);
        }
#pragma unroll
        for (int p = 0; p < 4; p++) {
            int row = p * 32 + ldr;
            uint32_t dst = smBase + 2 * TILE_B + buf * TILE_B + row * 128 + ((ldc ^ (row & 7)) << 4);
            cp_async16(dst, &BT[(size_t)(colBase + row) * K + k0 + ldc * 8]);
        }
    };

    float acc[2][8][4];
#pragma unroll
    for (int mt = 0; mt < 2; mt++)
#pragma unroll
        for (int nt = 0; nt < 8; nt++)
#pragma unroll
            for (int i = 0; i < 4; i++) acc[mt][nt][i] = 0.f;

    loadTile(0, 0);
    CP_COMMIT();

    const int lrow = lane & 15;
    const int khalf = lane >> 4;

#pragma unroll 1
    for (int it = 0; it < KITERS; ++it) {
        const int buf = it & 1;
        CP_WAIT0();
        __syncthreads();
        if (it + 1 < KITERS) {
            loadTile(it + 1, buf ^ 1);
            CP_COMMIT();
        }
        const uint32_t Abase = smBase + buf * TILE_B;
        const uint32_t Bbase = smBase + 2 * TILE_B + buf * TILE_B;
#pragma unroll
        for (int ks = 0; ks < 4; ks++) {
            const int cIdx = 2 * ks + khalf;
            uint32_t a[2][4];
#pragma unroll
            for (int mt = 0; mt < 2; mt++) {
                int row = warpM * 32 + mt * 16 + lrow;
                ldmatrix_x4(a[mt], Abase + row * 128 + ((cIdx ^ (row & 7)) << 4));
            }
            uint32_t br[4][4];
#pragma unroll
            for (int j = 0; j < 4; j++) {
                int row = warpN * 64 + j * 16 + lrow;
                ldmatrix_x4(br[j], Bbase + row * 128 + ((cIdx ^ (row & 7)) << 4));
            }
#pragma unroll
            for (int mt = 0; mt < 2; mt++)
#pragma unroll
                for (int j = 0; j < 4; j++) {
                    mma_f16(acc[mt][2 * j],     a[mt], br[j][0], br[j][2]);
                    mma_f16(acc[mt][2 * j + 1], a[mt], br[j][1], br[j][3]);
                }
        }
    }

    // ---- epilogue ----
    const bool stage = (OM == 3) && (colBase >= 512);   // k or v segment
    __half* sh = (__half*)smraw;
    if (stage) __syncthreads();

#pragma unroll
    for (int mt = 0; mt < 2; mt++) {
#pragma unroll
        for (int sub = 0; sub < 2; sub++) {
            const int rl = warpM * 32 + mt * 16 + g + sub * 8;
            const int r = rowBase + rl;
#pragma unroll
            for (int nt = 0; nt < 8; nt++) {
                const int cl = warpN * 64 + nt * 8 + 2 * t;
                const int c = colBase + cl;
                float2 o;
                o.x = acc[mt][nt][sub * 2 + 0];
                o.y = acc[mt][nt][sub * 2 + 1];
                float2 bi = *(const float2*)&bias[c];
                o.x += bi.x; o.y += bi.y;
                if (RES == 2) {
                    float2 rr = __half22float2(*(const __half2*)&resh[(size_t)r * N + c]);
                    o.x += rr.x; o.y += rr.y;
                }
                if (ACT == 1 || (ACT == 3 && c < 2 * DM)) {
                    o.x = (o.x > 0.f) ? (o.x + 1.f) : expf(o.x);
                    o.y = (o.y > 0.f) ? (o.y + 1.f) : expf(o.y);
                } else if (ACT == 2) {
                    o.x = fmaxf(o.x, 0.f);
                    o.y = fmaxf(o.y, 0.f);
                }
                if (OM == 3) {
                    if (!stage) {
                        *(__half2*)&Ch[(size_t)r * DM + c] = __floats2half2_rn(o.x, o.y);
                    } else {
                        sh[cl * TSTR + rl]       = __float2half(o.x);
                        sh[(cl + 1) * TSTR + rl] = __float2half(o.y);
                    }
                } else {
                    *(__half2*)&Ch[(size_t)r * N + c] = __floats2half2_rn(o.x, o.y);
                }
            }
        }
    }

    if (stage) {
        __syncthreads();
        const int seg = colBase >> 9;          // 1 = k, 2 = v
        const int rowd = tid >> 1;
        const int hs = tid & 1;
        const int hloc = rowd >> 6, d = rowd & 63;
        const int b = rowBase >> 12;
        const int s0 = rowBase & (SEQ - 1);
        const int hbase = (colBase & 511) >> 6;
        const int bh = b * NH + hbase + hloc;
        __half* dstT = (seg == 1) ? Ch2 : Ch3;
        const size_t rstr = (seg == 1) ? HD : KVXR;
        const uint4* s4 = (const uint4*)(sh + rowd * TSTR + hs * 64);
        uint4* d4 = (uint4*)(dstT + ((size_t)bh * rstr + d) * SEQ + s0 + hs * 64);
#pragma unroll
        for (int i = 0; i < 8; i++) d4[i] = s4[i];
    }
}

// ---------------- pad embeddings ----------------
__global__ void pad_emb_h(const float* __restrict__ in, __half* __restrict__ out) {
    int i = blockIdx.x * 256 + threadIdx.x;
    if (i >= BS * KPAD) return;
    int r = i / KPAD, c = i - r * KPAD;
    out[i] = (c < F_IN) ? __float2half(in[(size_t)r * F_IN + c]) : __half(0.f);
}

// ---------------- init vT tail rows ----------------
__global__ void init_vtail(__half* __restrict__ vT) {
    int i = blockIdx.x * 256 + threadIdx.x;
    if (i >= BH * 16 * SEQ) return;
    int bh = i / (16 * SEQ);
    int rem = i - bh * 16 * SEQ;
    int row = 64 + rem / SEQ;
    int s = rem % SEQ;
    vT[((size_t)bh * KVXR + row) * SEQ + s] = (row == 64) ? __half(1.f) : __half(0.f);
}

// ---------------- batched weight transpose ----------------
#define NTR 13
struct TrDesc { const float* in; __half* out; int K; int N; int KP; int tileStart; };
struct TrPack { TrDesc d[NTR]; };

__global__ void transpose_batch(TrPack p) {
    __shared__ float t[32][33];
    const int bt = blockIdx.x;
    int mi = 0;
#pragma unroll
    for (int i = 1; i < NTR; i++)
        if (bt >= p.d[i].tileStart) mi = i;
    const TrDesc de = p.d[mi];
    const int lt = bt - de.tileStart;
    const int ktiles = de.KP >> 5;
    const int k0 = (lt % ktiles) * 32;
    const int n0 = (lt / ktiles) * 32;
    const int x = threadIdx.x, y = threadIdx.y;
#pragma unroll
    for (int j = 0; j < 32; j += 8) {
        int kk = k0 + y + j;
        t[y + j][x] = (kk < de.K && n0 + x < de.N)
                      ? de.in[(size_t)kk * de.N + n0 + x] : 0.f;
    }
    __syncthreads();
#pragma unroll
    for (int j = 0; j < 32; j += 8)
        if (n0 + y + j < de.N)
            de.out[(size_t)(n0 + y + j) * de.KP + k0 + x] = __float2half(t[x][y + j]);
}

// ---------------- concat q/k/v biases ----------------
__global__ void concat_bias(const float* __restrict__ bq, const float* __restrict__ bk,
                            const float* __restrict__ bv, float* __restrict__ out) {
    int i = blockIdx.x * 256 + threadIdx.x;
    if (i >= NLAY * QKVN) return;
    int l = i / QKVN, c = i - l * QKVN;
    float v;
    if (c < DM)           v = bq[l * DM + c];
    else if (c < 2 * DM)  v = bk[l * DM + c - DM];
    else                  v = bv[l * DM + c - 2 * DM];
    out[i] = v;
}

// ---------------- kv partials via mma ----------------
__global__ __launch_bounds__(128) void kv_mma(
    const __half* __restrict__ kT, const __half* __restrict__ vT,
    float* __restrict__ kvpart)
{
    __shared__ __half smA[2][KVXR * 64];
    __shared__ __half smB[2][64 * 64];
    const uint32_t aBase0 = smem_u32(smA);
    const uint32_t bBase0 = smem_u32(smB);
    const int bh = blockIdx.x;
    const int chunk = blockIdx.y;
    const int tid = threadIdx.x;
    const int warp = tid >> 5;
    const int lane = tid & 31;
    const int g = lane >> 2, t = lane & 3;
    const int lrow = lane & 15, khalf = lane >> 4;
    const int s0 = chunk * KV_CH;

    const int ldr = tid >> 3;
    const int ldc = tid & 7;
    auto loadTile = [&](int it, int buf) {
        const int k0 = s0 + it * 64;
#pragma unroll
        for (int p = 0; p < 5; p++) {
            int row = p * 16 + ldr;
            uint32_t off = buf * (KVXR * 128) + row * 128 + ((ldc ^ (row & 7)) << 4);
            cp_async16(aBase0 + off, &vT[((size_t)bh * KVXR + row) * SEQ + k0 + ldc * 8]);
        }
#pragma unroll
        for (int p = 0; p < 4; p++) {
            int row = p * 16 + ldr;
            uint32_t off = buf * 8192 + row * 128 + ((ldc ^ (row & 7)) << 4);
            cp_async16(bBase0 + off, &kT[((size_t)bh * HD + row) * SEQ + k0 + ldc * 8]);
        }
    };

    float acc[5][2][4];
#pragma unroll
    for (int mt = 0; mt < 5; mt++)
#pragma unroll
        for (int j = 0; j < 2; j++)
#pragma unroll
            for (int i = 0; i < 4; i++) acc[mt][j][i] = 0.f;

    loadTile(0, 0);
    CP_COMMIT();

#pragma unroll 1
    for (int it = 0; it < KV_CH / 64; ++it) {
        const int buf = it & 1;
        CP_WAIT0();
        __syncthreads();
        if (it + 1 < KV_CH / 64) {
            loadTile(it + 1, buf ^ 1);
            CP_COMMIT();
        }
        const uint32_t Ab = aBase0 + buf * (KVXR * 128);
        const uint32_t Bb = bBase0 + buf * 8192;
#pragma unroll
        for (int ks = 0; ks < 4; ks++) {
            const int cIdx = 2 * ks + khalf;
            uint32_t a[5][4];
#pragma unroll
            for (int mt = 0; mt < 5; mt++) {
                int row = mt * 16 + lrow;
                ldmatrix_x4(a[mt], Ab + row * 128 + ((cIdx ^ (row & 7)) << 4));
            }
            uint32_t br[4];
            {
                int row = warp * 16 + lrow;
                ldmatrix_x4(br, Bb + row * 128 + ((cIdx ^ (row & 7)) << 4));
            }
#pragma unroll
            for (int mt = 0; mt < 5; mt++) {
                mma_f16(acc[mt][0], a[mt], br[0], br[2]);
                mma_f16(acc[mt][1], a[mt], br[1], br[3]);
            }
        }
    }

#pragma unroll
    for (int mt = 0; mt < 5; mt++)
#pragma unroll
        for (int j = 0; j < 2; j++)
#pragma unroll
            for (int sub = 0; sub < 2; sub++) {
                int m = mt * 16 + g + sub * 8;
                int d = warp * 16 + j * 8 + 2 * t;
                float2 o;
                o.x = acc[mt][j][sub * 2 + 0];
                o.y = acc[mt][j][sub * 2 + 1];
                *(float2*)&kvpart[(((size_t)chunk * BH + bh) * KVXR + m) * HD + d] = o;
            }
}

// ---------------- reduce partials -> kvx ----------------
__global__ __launch_bounds__(256) void reduce_kvx(
    const float* __restrict__ kvpart, __half* __restrict__ kvx)
{
    const int bh = blockIdx.x;
    for (int idx = threadIdx.x; idx < KVXR * HD; idx += 256) {
        float v = 0.f;
#pragma unroll
        for (int c = 0; c < NCHUNK; c++)
            v += kvpart[((size_t)c * BH + bh) * (KVXR * HD) + idx];
        kvx[(size_t)bh * (KVXR * HD) + idx] = __float2half(v);
    }
}

// ---------------- attention via mma ----------------
__global__ __launch_bounds__(128) void attn_mma(
    const __half* __restrict__ q, const __half* __restrict__ kvx,
    __half* __restrict__ out)
{
    __shared__ __half smA[64 * 64];
    __shared__ __half smB[KVXR * 64];
    const uint32_t aBase = smem_u32(smA);
    const uint32_t bBase = smem_u32(smB);
    const int bh = blockIdx.x;
    const int s0 = blockIdx.y * 64;
    const int b = bh >> 3, h = bh & 7;
    const int tid = threadIdx.x;
    const int warp = tid >> 5;
    const int lane = tid & 31;
    const int g = lane >> 2, t = lane & 3;
    const int lrow = lane & 15, khalf = lane >> 4;

    {
        const int ldr = tid >> 3, ldc = tid & 7;
#pragma unroll
        for (int p = 0; p < 4; p++) {
            int row = p * 16 + ldr;
            uint32_t dst = aBase + row * 128 + ((ldc ^ (row & 7)) << 4);
            cp_async16(dst, &q[(size_t)(b * SEQ + s0 + row) * DM + h * HD + ldc * 8]);
        }
#pragma unroll
        for (int p = 0; p < 5; p++) {
            int row = p * 16 + ldr;
            uint32_t dst = bBase + row * 128 + ((ldc ^ (row & 7)) << 4);
            cp_async16(dst, &kvx[((size_t)bh * KVXR + row) * HD + ldc * 8]);
        }
        CP_COMMIT();
        CP_WAIT0();
        __syncthreads();
    }

    float acc[10][4];
#pragma unroll
    for (int nt = 0; nt < 10; nt++)
#pragma unroll
        for (int i = 0; i < 4; i++) acc[nt][i] = 0.f;

#pragma unroll
    for (int ks = 0; ks < 4; ks++) {
        const int cIdx = 2 * ks + khalf;
        uint32_t a[4];
        {
            int row = warp * 16 + lrow;
            ldmatrix_x4(a, aBase + row * 128 + ((cIdx ^ (row & 7)) << 4));
        }
#pragma unroll
        for (int j = 0; j < 5; j++) {
            uint32_t br[4];
            int row = j * 16 + lrow;
            ldmatrix_x4(br, bBase + row * 128 + ((cIdx ^ (row & 7)) << 4));
            mma_f16(acc[2 * j],     a, br[0], br[2]);
            mma_f16(acc[2 * j + 1], a, br[1], br[3]);
        }
    }

    float d0 = __shfl_sync(0xffffffffu, acc[8][0], lane & 28);
    float d1 = __shfl_sync(0xffffffffu, acc[8][2], lane & 28);
    float z0 = 1.f / (d0 + EPS_ATTN);
    float z1 = 1.f / (d1 + EPS_ATTN);

    const int r0 = s0 + warp * 16 + g;
#pragma unroll
    for (int nt = 0; nt < 8; nt++) {
        int c = nt * 8 + 2 * t;
        *(__half2*)&out[(size_t)(b * SEQ + r0) * DM + h * HD + c] =
            __floats2half2_rn(acc[nt][0] * z0, acc[nt][1] * z0);
        *(__half2*)&out[(size_t)(b * SEQ + r0 + 8) * DM + h * HD + c] =
            __floats2half2_rn(acc[nt][2] * z1, acc[nt][3] * z1);
    }
}

// ---------------- block reduce helper ----------------
__device__ __forceinline__ float bsum128(float v, float* sm) {
#pragma unroll
    for (int o = 16; o > 0; o >>= 1) v += __shfl_down_sync(0xffffffffu, v, o);
    int w = threadIdx.x >> 5;
    if ((threadIdx.x & 31) == 0) sm[w] = v;
    __syncthreads();
    float r = sm[0] + sm[1] + sm[2] + sm[3];
    __syncthreads();
    return r;
}

// ---------------- layernorm: fp16 in -> fp16 out ----------------
__global__ __launch_bounds__(128) void ln_kernel(
    const __half* __restrict__ in, const float* __restrict__ g,
    const float* __restrict__ b, __half* __restrict__ hout)
{
    __shared__ float sm[4];
    const int row = blockIdx.x;
    const int tid = threadIdx.x;
    uint2 raw = ((const uint2*)(in + (size_t)row * DM))[tid];
    float2 f0 = __half22float2(*(__half2*)&raw.x);
    float2 f1 = __half22float2(*(__half2*)&raw.y);
    float s  = f0.x + f0.y + f1.x + f1.y;
    float sq = f0.x * f0.x + f0.y * f0.y + f1.x * f1.x + f1.y * f1.y;
    s  = bsum128(s, sm);
    sq = bsum128(sq, sm);
    float mu = s * (1.f / DM);
    float var = sq * (1.f / DM) - mu * mu;
    float rstd = rsqrtf(var + EPS_LN);
    float4 gg = ((const float4*)g)[tid];
    float4 bb = ((const float4*)b)[tid];
    float ox = (f0.x - mu) * rstd * gg.x + bb.x;
    float oy = (f0.y - mu) * rstd * gg.y + bb.y;
    float oz = (f1.x - mu) * rstd * gg.z + bb.z;
    float ow = (f1.y - mu) * rstd * gg.w + bb.w;
    uint2 pk;
    *(__half2*)&pk.x = __floats2half2_rn(ox, oy);
    *(__half2*)&pk.y = __floats2half2_rn(oz, ow);
    ((uint2*)(hout + (size_t)row * DM))[tid] = pk;
}

// ---------------- fused final LN + out proj (fp16 in) ----------------
__global__ __launch_bounds__(128) void final_kernel(
    const __half* __restrict__ in, const float* __restrict__ g,
    const float* __restrict__ b, const float* __restrict__ w,
    const float* __restrict__ bout, float* __restrict__ out)
{
    __shared__ float sm[4];
    const int row = blockIdx.x;
    const int tid = threadIdx.x;
    uint2 raw = ((const uint2*)(in + (size_t)row * DM))[tid];
    float2 f0 = __half22float2(*(__half2*)&raw.x);
    float2 f1 = __half22float2(*(__half2*)&raw.y);
    float s  = f0.x + f0.y + f1.x + f1.y;
    float sq = f0.x * f0.x + f0.y * f0.y + f1.x * f1.x + f1.y * f1.y;
    s  = bsum128(s, sm);
    sq = bsum128(sq, sm);
    float mu = s * (1.f / DM);
    float var = sq * (1.f / DM) - mu * mu;
    float rstd = rsqrtf(var + EPS_LN);
    float4 gg = ((const float4*)g)[tid];
    float4 bb = ((const float4*)b)[tid];
    float4 ww = ((const float4*)w)[tid];
    float acc = ((f0.x - mu) * rstd * gg.x + bb.x) * ww.x
              + ((f0.y - mu) * rstd * gg.y + bb.y) * ww.y
              + ((f1.x - mu) * rstd * gg.z + bb.z) * ww.z
              + ((f1.y - mu) * rstd * gg.w + bb.w) * ww.w;
    acc = bsum128(acc, sm);
    if (tid == 0) out[row] = acc + bout[0];
}

extern "C" void kernel_launch(void* const* d_in, const int* in_sizes, int n_in,
                              void* d_out, int out_size)
{
    const float* emb   = (const float*)d_in[0];
    const float* W0    = (const float*)d_in[1];
    const float* b0    = (const float*)d_in[2];
    const float* Wq    = (const float*)d_in[3];
    const float* bq    = (const float*)d_in[4];
    const float* Wk    = (const float*)d_in[5];
    const float* bk    = (const float*)d_in[6];
    const float* Wv    = (const float*)d_in[7];
    const float* bv    = (const float*)d_in[8];
    const float* Wo    = (const float*)d_in[9];
    const float* bo    = (const float*)d_in[10];
    const float* ln1s  = (const float*)d_in[11];
    const float* ln1b  = (const float*)d_in[12];
    const float* W1    = (const float*)d_in[13];
    const float* b1    = (const float*)d_in[14];
    const float* W2    = (const float*)d_in[15];
    const float* b2    = (const float*)d_in[16];
    const float* ln2s  = (const float*)d_in[17];
    const float* ln2b  = (const float*)d_in[18];
    const float* lnfs  = (const float*)d_in[19];
    const float* lnfb  = (const float*)d_in[20];
    const float* Wout  = (const float*)d_in[21];
    const float* bout  = (const float*)d_in[22];
    float* out = (float*)d_out;

    auto gemm_in   = gemm_t<10, DM,   0, 0, 1>;
    auto gemm_qkv  = gemm_t<8,  QKVN, 3, 0, 3>;
    auto gemm_wo   = gemm_t<8,  DM,   0, 2, 1>;
    auto gemm_ffn1 = gemm_t<8,  FF,   2, 0, 1>;
    auto gemm_ffn2 = gemm_t<16, DM,   0, 2, 1>;
    cudaFuncSetAttribute(gemm_in,   cudaFuncAttributeMaxDynamicSharedMemorySize, GEMM_SMEM);
    cudaFuncSetAttribute(gemm_qkv,  cudaFuncAttributeMaxDynamicSharedMemorySize, GEMM_SMEM);
    cudaFuncSetAttribute(gemm_wo,   cudaFuncAttributeMaxDynamicSharedMemorySize, GEMM_SMEM);
    cudaFuncSetAttribute(gemm_ffn1, cudaFuncAttributeMaxDynamicSharedMemorySize, GEMM_SMEM);
    cudaFuncSetAttribute(gemm_ffn2, cudaFuncAttributeMaxDynamicSharedMemorySize, GEMM_SMEM);

    __half *he, *hx, *hy, *hq, *ht, *hh, *kT, *vT, *kvx;
    __half *w0t, *wqkvt, *wot, *w1t, *w2t;
    float *pkvp, *bqkv;
    cudaGetSymbolAddress((void**)&he,  g_he);
    cudaGetSymbolAddress((void**)&hx,  g_hx);
    cudaGetSymbolAddress((void**)&hy,  g_hy);
    cudaGetSymbolAddress((void**)&hq,  g_hq);
    cudaGetSymbolAddress((void**)&ht,  g_ht);
    cudaGetSymbolAddress((void**)&hh,  g_hh);
    cudaGetSymbolAddress((void**)&kT,  g_kT);
    cudaGetSymbolAddress((void**)&vT,  g_vT);
    cudaGetSymbolAddress((void**)&kvx, g_kvx);
    cudaGetSymbolAddress((void**)&pkvp, g_kvpart);
    cudaGetSymbolAddress((void**)&w0t, g_w0t);
    cudaGetSymbolAddress((void**)&wqkvt, g_wqkvt);
    cudaGetSymbolAddress((void**)&wot, g_wot);
    cudaGetSymbolAddress((void**)&w1t, g_w1t);
    cudaGetSymbolAddress((void**)&w2t, g_w2t);
    cudaGetSymbolAddress((void**)&bqkv, g_bqkv);

    // ---- prep ----
    pad_emb_h<<<(BS * KPAD + 255) / 256, 256>>>(emb, he);
    concat_bias<<<(NLAY * QKVN + 255) / 256, 256>>>(bq, bk, bv, bqkv);
    init_vtail<<<(BH * 16 * SEQ + 255) / 256, 256>>>(vT);

    TrPack pack;
    int tileOff = 0;
    auto addTr = [&](int idx, const float* in, __half* outp, int K, int N, int KP) {
        pack.d[idx].in = in; pack.d[idx].out = outp;
        pack.d[idx].K = K; pack.d[idx].N = N; pack.d[idx].KP = KP;
        pack.d[idx].tileStart = tileOff;
        tileOff += (KP / 32) * ((N + 31) / 32);
    };
    int di = 0;
    addTr(di++, W0, w0t, F_IN, DM, KPAD);
    for (int l = 0; l < NLAY; l++) {
        __half* wl = wqkvt + (size_t)l * QKVN * DM;
        addTr(di++, Wq + (size_t)l * DM * DM, wl,                        DM, DM, DM);
        addTr(di++, Wk + (size_t)l * DM * DM, wl + (size_t)DM * DM,      DM, DM, DM);
        addTr(di++, Wv + (size_t)l * DM * DM, wl + (size_t)2 * DM * DM,  DM, DM, DM);
        addTr(di++, Wo + (size_t)l * DM * DM, wot + (size_t)l * DM * DM, DM, DM, DM);
        addTr(di++, W1 + (size_t)l * DM * FF, w1t + (size_t)l * DM * FF, DM, FF, DM);
        addTr(di++, W2 + (size_t)l * FF * DM, w2t + (size_t)l * FF * DM, FF, DM, FF);
    }
    transpose_batch<<<tileOff, dim3(32, 8)>>>(pack);

    // ---- input projection -> hx fp16 ----
    gemm_in<<<dim3(DM / GBN, BS / GBM), 256, GEMM_SMEM>>>(
        he, w0t, b0, nullptr, hx, nullptr, nullptr);

    for (int l = 0; l < NLAY; l++) {
        const __half* wqkv_l = wqkvt + (size_t)l * QKVN * DM;
        const __half* wot_l  = wot + (size_t)l * DM * DM;
        const __half* w1t_l  = w1t + (size_t)l * DM * FF;
        const __half* w2t_l  = w2t + (size_t)l * FF * DM;
        const float* bqkv_l = bqkv + (size_t)l * QKVN;
        const float* bo_l = bo + (size_t)l * DM;
        const float* b1_l = b1 + (size_t)l * FF;
        const float* b2_l = b2 + (size_t)l * DM;

        gemm_qkv<<<dim3(QKVN / GBN, BS / GBM), 256, GEMM_SMEM>>>(
            hx, wqkv_l, bqkv_l, nullptr, hq, kT, vT);

        kv_mma<<<dim3(BH, NCHUNK), 128>>>(kT, vT, pkvp);
        reduce_kvx<<<BH, 256>>>(pkvp, kvx);
        attn_mma<<<dim3(BH, SEQ / 64), 128>>>(hq, kvx, ht);

        gemm_wo<<<dim3(DM / GBN, BS / GBM), 256, GEMM_SMEM>>>(
            ht, wot_l, bo_l, hx, hy, nullptr, nullptr);
        ln_kernel<<<BS, 128>>>(hy, ln1s + (size_t)l * DM, ln1b + (size_t)l * DM, hx);

        gemm_ffn1<<<dim3(FF / GBN, BS / GBM), 256, GEMM_SMEM>>>(
            hx, w1t_l, b1_l, nullptr, hh, nullptr, nullptr);
        gemm_ffn2<<<dim3(DM / GBN, BS / GBM), 256, GEMM_SMEM>>>(
            hh, w2t_l, b2_l, hx, hy, nullptr, nullptr);
        ln_kernel<<<BS, 128>>>(hy, ln2s + (size_t)l * DM, ln2b + (size_t)l * DM, hx);
    }

    final_kernel<<<BS, 128>>>(hx, lnfs, lnfb, Wout, bout, out);
}